// round 14
// baseline (speedup 1.0000x reference)
#include <cuda_runtime.h>
#include <cuda_fp16.h>
#include <cstdint>

#define N_NODES 50000
#define N_EDGES 800000
#define DIM 256
#define N_GRAPHS 500
#define N_OUT 10
#define BN_EPS 1e-5f

#define N_TILES 391              // ceil(50000/128)
#define TILE_BYTES 131072        // full split planes: 8 chunks * (hi 8KB + lo 8KB)
#define HTILE_BYTES 65536        // compact hi planes: 8 chunks * 8KB

// ---------------- scratch ----------------
__device__ unsigned char g_pl0[(size_t)N_TILES * TILE_BYTES];
__device__ unsigned char g_pl1[(size_t)N_TILES * TILE_BYTES];
__device__ unsigned char g_hp1[(size_t)N_TILES * HTILE_BYTES];
__device__ unsigned char g_hp2[(size_t)N_TILES * HTILE_BYTES];
__device__ float g_pool[(size_t)N_GRAPHS * 2 * DIM];
__device__ int   g_idx_is64;
__device__ int   g_counts[N_NODES];
__device__ int   g_rowptr[N_NODES + 1];
__device__ int   g_cursor[N_NODES];
__device__ int   g_esrc[N_EDGES];
__device__ int   g_partials[64];
// weights (single fp16): [slot][chunk=8][nhalf=2][8192B] = 128KB/slot
__device__ unsigned char g_wt[4 * 131072];

// ---------------- helpers ----------------
__device__ __forceinline__ uint32_t smem_u32(const void* p) {
    uint32_t a;
    asm("{ .reg .u64 t; cvta.to.shared.u64 t, %1; cvt.u32.u64 %0, t; }" : "=r"(a) : "l"(p));
    return a;
}
__device__ __forceinline__ void cp16(uint32_t s, const void* g) {
    asm volatile("cp.async.cg.shared.global [%0], [%1], 16;"
                 :: "r"(s), "l"(__cvta_generic_to_global(g)) : "memory");
}
__device__ __forceinline__ void cp_commit() { asm volatile("cp.async.commit_group;" ::: "memory"); }
__device__ __forceinline__ void ldx4(uint32_t* r, uint32_t addr) {
    asm volatile("ldmatrix.sync.aligned.m8n8.x4.shared.b16 {%0,%1,%2,%3}, [%4];"
                 : "=r"(r[0]), "=r"(r[1]), "=r"(r[2]), "=r"(r[3]) : "r"(addr));
}
__device__ __forceinline__ void ldx2(uint32_t* r, uint32_t addr) {
    asm volatile("ldmatrix.sync.aligned.m8n8.x2.shared.b16 {%0,%1}, [%2];"
                 : "=r"(r[0]), "=r"(r[1]) : "r"(addr));
}
__device__ __forceinline__ void mma16816h(float* d, const uint32_t* a, const uint32_t* b) {
    asm volatile("mma.sync.aligned.m16n8k16.row.col.f32.f16.f16.f32 "
                 "{%0,%1,%2,%3}, {%4,%5,%6,%7}, {%8,%9}, {%0,%1,%2,%3};"
                 : "+f"(d[0]), "+f"(d[1]), "+f"(d[2]), "+f"(d[3])
                 : "r"(a[0]), "r"(a[1]), "r"(a[2]), "r"(a[3]), "r"(b[0]), "r"(b[1]));
}
__device__ __forceinline__ uint32_t tswz(int r, int ccol) {
    int rr = r >> 1;
    return ((uint32_t)rr << 7) + ((uint32_t)((ccol + ((r & 1) << 2)) ^ (rr & 7)) << 4);
}
__device__ __forceinline__ uint32_t packhf2(float a, float b) {
    __half2 h = __floats2half2_rn(a, b);
    return *(uint32_t*)&h;
}
__device__ __forceinline__ void plane_row_load(const unsigned char* P, int s, int lane,
                                               float4& v0, float4& v1) {
    int tile = s >> 7, r = s & 127;
    int ccol = (lane >> 1) & 3, c0 = lane >> 3;
    uint32_t off = tswz(r, ccol) + (uint32_t)(lane & 1) * 8;
    const unsigned char* base = P + (size_t)tile * HTILE_BYTES;
    uint2 u0 = *(const uint2*)(base + (size_t)c0 * 8192 + off);
    uint2 u1 = *(const uint2*)(base + (size_t)(c0 + 4) * 8192 + off);
    float2 f;
    f = __half22float2(*(__half2*)&u0.x); v0.x = f.x; v0.y = f.y;
    f = __half22float2(*(__half2*)&u0.y); v0.z = f.x; v0.w = f.y;
    f = __half22float2(*(__half2*)&u1.x); v1.x = f.x; v1.y = f.y;
    f = __half22float2(*(__half2*)&u1.y); v1.z = f.x; v1.w = f.y;
}

// ---------------- dtype detection ----------------
__device__ __forceinline__ int load_idx(const void* p, int i) {
    if (g_idx_is64) return (int)((const long long*)p)[i];
    return ((const int*)p)[i];
}

// ---------------- detect + zero counts (fused) ----------------
__global__ void detect_zero_kernel(const long long* __restrict__ ei) {
    int i = blockIdx.x * blockDim.x + threadIdx.x;
    if (i < N_NODES) g_counts[i] = 0;
    if (i == 0) {
        int ok = 1;
        for (int j = 0; j < 64; j++) {
            long long v = ei[j];
            if (v < 0 || v >= N_NODES) ok = 0;
        }
        g_idx_is64 = ok;
    }
}

// ---------------- fused weight-conv + histogram + pool-zero ----------------
// blocks [0,1024): wconv (4 slots x 256 blocks); blocks [1024, 1024+3125): hist.
#define WCONV_BLOCKS 1024
#define HIST_BLOCKS  3125
__global__ void prep_kernel(const void* __restrict__ ei,
                            const float* __restrict__ Wa, const float* __restrict__ Wb,
                            const float* __restrict__ Wc, const float* __restrict__ Wd) {
    int b = blockIdx.x;
    if (b < WCONV_BLOCKS) {
        int slot = b >> 8;
        const float* W = (slot == 0) ? Wa : (slot == 1) ? Wb : (slot == 2) ? Wc : Wd;
        int id = (b & 255) * 256 + threadIdx.x;   // 0..65535
        int k = id >> 8, n = id & 255;
        float v = W[(size_t)k * 256 + n];
        int c = k >> 5, kl = k & 31, h = n >> 7, r = n & 127;
        uint32_t off = tswz(r, kl >> 3) + (uint32_t)(kl & 7) * 2;
        size_t base = (size_t)slot * 131072 + (size_t)c * 16384 + (size_t)h * 8192;
        *(__half*)(g_wt + base + off) = __float2half_rn(v);
    } else {
        int e = (b - WCONV_BLOCKS) * 256 + threadIdx.x;
        if (e < N_GRAPHS * 2 * DIM) g_pool[e] = 0.f;
        if (e >= N_EDGES) return;
        atomicAdd(&g_counts[load_idx(ei, N_EDGES + e)], 1);
    }
}

__global__ void scan1_kernel() {
    __shared__ int wsum[32];
    int tid = threadIdx.x;
    int i = blockIdx.x * 1024 + tid;
    int v = (i < N_NODES) ? g_counts[i] : 0;
    int s = v;
    int lane = tid & 31;
#pragma unroll
    for (int o = 1; o < 32; o <<= 1) {
        int t = __shfl_up_sync(0xffffffffu, s, o);
        if (lane >= o) s += t;
    }
    if (lane == 31) wsum[tid >> 5] = s;
    __syncthreads();
    if (tid < 32) {
        int ws = wsum[tid];
#pragma unroll
        for (int o = 1; o < 32; o <<= 1) {
            int t = __shfl_up_sync(0xffffffffu, ws, o);
            if (tid >= o) ws += t;
        }
        wsum[tid] = ws;
    }
    __syncthreads();
    int off = (tid >= 32) ? wsum[(tid >> 5) - 1] : 0;
    int incl = s + off;
    if (i < N_NODES) g_rowptr[i] = incl - v;
    if (tid == 1023) g_partials[blockIdx.x] = incl;
}
__global__ void scan3_kernel(int nblk) {
    __shared__ int soff;
    int tid = threadIdx.x;
    if (tid < 32) {
        int acc = 0;
        int j0 = tid, j1 = tid + 32;
        if (j0 < nblk && j0 < blockIdx.x) acc += g_partials[j0];
        if (j1 < nblk && j1 < blockIdx.x) acc += g_partials[j1];
#pragma unroll
        for (int o = 16; o > 0; o >>= 1) acc += __shfl_down_sync(0xffffffffu, acc, o);
        if (tid == 0) soff = acc;
    }
    __syncthreads();
    int i = blockIdx.x * 1024 + tid;
    if (i < N_NODES) {
        int r = g_rowptr[i] + soff;
        g_rowptr[i] = r;
        g_cursor[i] = r;
    }
    if (i == 0) g_rowptr[N_NODES] = N_EDGES;
}
__global__ void fill_kernel(const void* __restrict__ ei) {
    int e = blockIdx.x * blockDim.x + threadIdx.x;
    if (e >= N_EDGES) return;
    int s = load_idx(ei, e);
    int d = load_idx(ei, N_EDGES + e);
    g_esrc[atomicAdd(&g_cursor[d], 1)] = s;
}

// ---------------- gather aggregation -> split-fp16 swizzled planes ----------------
// 4-way neighbor unroll: four rows' loads issued before accumulation (MLP x4).
template <bool IN_PLANES>
__global__ __launch_bounds__(256) void agg_kernel(const float* __restrict__ x,
                                                  const unsigned char* __restrict__ Ip,
                                                  unsigned char* __restrict__ Op) {
    int node = blockIdx.x * 8 + (threadIdx.x >> 5);
    if (node >= N_NODES) return;
    int lane = threadIdx.x & 31;
    const float4* xv = (const float4*)x;
    float4 acc0, acc1;
    if (IN_PLANES) {
        plane_row_load(Ip, node, lane, acc0, acc1);
    } else {
        acc0 = xv[(size_t)node * 64 + lane];
        acc1 = xv[(size_t)node * 64 + 32 + lane];
    }
    int start = g_rowptr[node];
    int end   = g_rowptr[node + 1];
    int k = start;
    for (; k + 3 < end; k += 4) {
        int s0 = g_esrc[k], s1 = g_esrc[k + 1], s2 = g_esrc[k + 2], s3 = g_esrc[k + 3];
        float4 a0, a1, b0, b1, c0v, c1v, d0, d1;
        if (IN_PLANES) {
            plane_row_load(Ip, s0, lane, a0, a1);
            plane_row_load(Ip, s1, lane, b0, b1);
            plane_row_load(Ip, s2, lane, c0v, c1v);
            plane_row_load(Ip, s3, lane, d0, d1);
        } else {
            const float4* x0 = xv + (size_t)s0 * 64;
            const float4* x1 = xv + (size_t)s1 * 64;
            const float4* x2 = xv + (size_t)s2 * 64;
            const float4* x3 = xv + (size_t)s3 * 64;
            a0 = x0[lane]; a1 = x0[lane + 32];
            b0 = x1[lane]; b1 = x1[lane + 32];
            c0v = x2[lane]; c1v = x2[lane + 32];
            d0 = x3[lane]; d1 = x3[lane + 32];
        }
        acc0.x += (a0.x + b0.x) + (c0v.x + d0.x);
        acc0.y += (a0.y + b0.y) + (c0v.y + d0.y);
        acc0.z += (a0.z + b0.z) + (c0v.z + d0.z);
        acc0.w += (a0.w + b0.w) + (c0v.w + d0.w);
        acc1.x += (a1.x + b1.x) + (c1v.x + d1.x);
        acc1.y += (a1.y + b1.y) + (c1v.y + d1.y);
        acc1.z += (a1.z + b1.z) + (c1v.z + d1.z);
        acc1.w += (a1.w + b1.w) + (c1v.w + d1.w);
    }
    for (; k < end; k++) {
        int sa = g_esrc[k];
        float4 a0, a1;
        if (IN_PLANES) {
            plane_row_load(Ip, sa, lane, a0, a1);
        } else {
            const float4* xa = xv + (size_t)sa * 64;
            a0 = xa[lane]; a1 = xa[lane + 32];
        }
        acc0.x += a0.x; acc0.y += a0.y; acc0.z += a0.z; acc0.w += a0.w;
        acc1.x += a1.x; acc1.y += a1.y; acc1.z += a1.z; acc1.w += a1.w;
    }
    int tile = node >> 7, r = node & 127;
    int ccol = (lane >> 1) & 3;
    int c0 = lane >> 3;
    uint32_t off = tswz(r, ccol) + (uint32_t)(lane & 1) * 8;
    unsigned char* base = Op + (size_t)tile * TILE_BYTES;
    float hx, hy;
    uint32_t h0 = packhf2(acc0.x, acc0.y), h1 = packhf2(acc0.z, acc0.w);
    hx = __half2float(__float2half_rn(acc0.x)); hy = __half2float(__float2half_rn(acc0.y));
    uint32_t l0 = packhf2(acc0.x - hx, acc0.y - hy);
    hx = __half2float(__float2half_rn(acc0.z)); hy = __half2float(__float2half_rn(acc0.w));
    uint32_t l1 = packhf2(acc0.z - hx, acc0.w - hy);
    *(uint2*)(base + (size_t)c0 * 16384 + off)        = make_uint2(h0, h1);
    *(uint2*)(base + (size_t)c0 * 16384 + 8192 + off) = make_uint2(l0, l1);
    uint32_t h2 = packhf2(acc1.x, acc1.y), h3 = packhf2(acc1.z, acc1.w);
    hx = __half2float(__float2half_rn(acc1.x)); hy = __half2float(__float2half_rn(acc1.y));
    uint32_t l2 = packhf2(acc1.x - hx, acc1.y - hy);
    hx = __half2float(__float2half_rn(acc1.z)); hy = __half2float(__float2half_rn(acc1.w));
    uint32_t l3 = packhf2(acc1.z - hx, acc1.w - hy);
    *(uint2*)(base + (size_t)(c0 + 4) * 16384 + off)        = make_uint2(h2, h3);
    *(uint2*)(base + (size_t)(c0 + 4) * 16384 + 8192 + off) = make_uint2(l2, l3);
}

// ---------------- pipelined split-fp16 tensor-core GEMM (2 passes) ----------------
#define STAGE_BYTES 24576
#define GSM_BYTES (2 * STAGE_BYTES + 1024)

template <bool DO_BN, int OMODE>
__global__ __launch_bounds__(256, 2) void gemm_mma_kernel(
    const unsigned char* __restrict__ Ap, const unsigned char* __restrict__ Wslot,
    const float* __restrict__ bias,
    const float* __restrict__ gamma, const float* __restrict__ beta,
    const float* __restrict__ mean,  const float* __restrict__ var,
    unsigned char* __restrict__ Oplanes, int M)
{
    extern __shared__ char dsm[];
    uint32_t sb0 = smem_u32(dsm);
    uint32_t sb = (sb0 + 1023u) & ~1023u;

    const int tid = threadIdx.x, wid = tid >> 5, lane = tid & 31;
    const int rowBase = blockIdx.x * 128;
    const int nh = blockIdx.y;
    const int wm = (wid >> 2) * 64;
    const int wn = (wid & 3) * 32;

    const int lr = lane & 7;
    const int ag = lane >> 3;
    const int aRowOff = (ag & 1) * 8 + lr;
    const int aCc = ag >> 1;
    const int bCc = (lane >> 3) & 1;

    uint32_t aBase[4], bBase[4];
    int aXor[4], aS4[4], bXor[4], bS4[4];
#pragma unroll
    for (int mi = 0; mi < 4; mi++) {
        int r = wm + mi * 16 + aRowOff;
        aBase[mi] = (uint32_t)(r >> 1) << 7;
        aXor[mi] = (r >> 1) & 7;
        aS4[mi] = (r & 1) << 2;
    }
#pragma unroll
    for (int ni = 0; ni < 4; ni++) {
        int r = wn + ni * 8 + lr;
        bBase[ni] = (uint32_t)(r >> 1) << 7;
        bXor[ni] = (r >> 1) & 7;
        bS4[ni] = (r & 1) << 2;
    }

    float acc[4][4][4];
#pragma unroll
    for (int mi = 0; mi < 4; mi++)
#pragma unroll
        for (int ni = 0; ni < 4; ni++)
#pragma unroll
            for (int q = 0; q < 4; q++) acc[mi][ni][q] = 0.f;

    const unsigned char* Asrc = Ap + (size_t)blockIdx.x * TILE_BYTES;
    const unsigned char* Bsrc0 = Wslot + (size_t)nh * 8192;

    {
#pragma unroll
        for (int j = 0; j < 4; j++) {
            int idx = tid + j * 256;
            cp16(sb + idx * 16, Asrc + idx * 16);
        }
#pragma unroll
        for (int j = 0; j < 2; j++) {
            int idx = tid + j * 256;
            cp16(sb + 16384 + idx * 16, Bsrc0 + idx * 16);
        }
        cp_commit();
    }

    for (int c = 0; c < 8; c++) {
        int p = c & 1;
        if (c < 7) {
            uint32_t sB = sb + (p ^ 1) * STAGE_BYTES;
            const unsigned char* ga = Asrc + (size_t)(c + 1) * 16384;
            const unsigned char* gb = Bsrc0 + (size_t)(c + 1) * 16384;
#pragma unroll
            for (int j = 0; j < 4; j++) {
                int idx = tid + j * 256;
                cp16(sB + idx * 16, ga + idx * 16);
            }
#pragma unroll
            for (int j = 0; j < 2; j++) {
                int idx = tid + j * 256;
                cp16(sB + 16384 + idx * 16, gb + idx * 16);
            }
            cp_commit();
            asm volatile("cp.async.wait_group 1;" ::: "memory");
        } else {
            asm volatile("cp.async.wait_group 0;" ::: "memory");
        }
        __syncthreads();

        uint32_t bufb = sb + p * STAGE_BYTES;
        uint32_t sA_hi = bufb;
        uint32_t sA_lo = bufb + 8192;
        uint32_t sB    = bufb + 16384;

#pragma unroll
        for (int ks = 0; ks < 2; ks++) {
            int ka = ks * 2 + aCc;
            int kb = ks * 2 + bCc;
            uint32_t ah[4][4];
#pragma unroll
            for (int mi = 0; mi < 4; mi++)
                ldx4(ah[mi], sA_hi + aBase[mi] + ((uint32_t)((ka + aS4[mi]) ^ aXor[mi]) << 4));
            uint32_t b[4][2];
#pragma unroll
            for (int ni = 0; ni < 4; ni++)
                ldx2(b[ni], sB + bBase[ni] + ((uint32_t)((kb + bS4[ni]) ^ bXor[ni]) << 4));
#pragma unroll
            for (int mi = 0; mi < 4; mi++)
#pragma unroll
                for (int ni = 0; ni < 4; ni++) mma16816h(acc[mi][ni], ah[mi], b[ni]);
#pragma unroll
            for (int mi = 0; mi < 4; mi++) {
                uint32_t at[4];
                ldx4(at, sA_lo + aBase[mi] + ((uint32_t)((ka + aS4[mi]) ^ aXor[mi]) << 4));
#pragma unroll
                for (int ni = 0; ni < 4; ni++) mma16816h(acc[mi][ni], at, b[ni]);
            }
        }
        __syncthreads();
    }

    // ---- epilogue ----
    float sc[4][2], sh[4][2];
#pragma unroll
    for (int ni = 0; ni < 4; ni++) {
#pragma unroll
        for (int j = 0; j < 2; j++) {
            int col = nh * 128 + wn + ni * 8 + (lane & 3) * 2 + j;
            float bv = bias[col];
            if (DO_BN) {
                float s = gamma[col] * rsqrtf(var[col] + BN_EPS);
                sc[ni][j] = s;
                sh[ni][j] = beta[col] - mean[col] * s + bv * s;
            } else {
                sc[ni][j] = 1.f;
                sh[ni][j] = bv;
            }
        }
    }
#pragma unroll
    for (int mi = 0; mi < 4; mi++) {
        int rl0 = wm + mi * 16 + (lane >> 2);
        int rl1 = rl0 + 8;
#pragma unroll
        for (int ni = 0; ni < 4; ni++) {
            int c0g = nh * 128 + wn + ni * 8 + (lane & 3) * 2;
            float v0 = fmaxf(acc[mi][ni][0] * sc[ni][0] + sh[ni][0], 0.f);
            float v1 = fmaxf(acc[mi][ni][1] * sc[ni][1] + sh[ni][1], 0.f);
            float v2 = fmaxf(acc[mi][ni][2] * sc[ni][0] + sh[ni][0], 0.f);
            float v3 = fmaxf(acc[mi][ni][3] * sc[ni][1] + sh[ni][1], 0.f);
            int ch = c0g >> 5, kl = c0g & 31;
            uint32_t bib = (uint32_t)(kl & 7) * 2;
            if (OMODE == 1) {
                unsigned char* tb = Oplanes + (size_t)blockIdx.x * TILE_BYTES + (size_t)ch * 16384;
                if (rowBase + rl0 < M) {
                    uint32_t off = tswz(rl0, kl >> 3) + bib;
                    float h0 = __half2float(__float2half_rn(v0));
                    float h1 = __half2float(__float2half_rn(v1));
                    *(uint32_t*)(tb + off)        = packhf2(v0, v1);
                    *(uint32_t*)(tb + 8192 + off) = packhf2(v0 - h0, v1 - h1);
                }
                if (rowBase + rl1 < M) {
                    uint32_t off = tswz(rl1, kl >> 3) + bib;
                    float h2 = __half2float(__float2half_rn(v2));
                    float h3 = __half2float(__float2half_rn(v3));
                    *(uint32_t*)(tb + off)        = packhf2(v2, v3);
                    *(uint32_t*)(tb + 8192 + off) = packhf2(v2 - h2, v3 - h3);
                }
            } else {
                unsigned char* tb = Oplanes + (size_t)blockIdx.x * HTILE_BYTES + (size_t)ch * 8192;
                if (rowBase + rl0 < M)
                    *(uint32_t*)(tb + tswz(rl0, kl >> 3) + bib) = packhf2(v0, v1);
                if (rowBase + rl1 < M)
                    *(uint32_t*)(tb + tswz(rl1, kl >> 3) + bib) = packhf2(v2, v3);
            }
        }
    }
}

// ---------------- pooling (reads compact hi planes; R11 layout) ----------------
__global__ void pool_kernel(const unsigned char* __restrict__ hp1,
                            const unsigned char* __restrict__ hp2,
                            const void* __restrict__ batch) {
    int wid = blockIdx.x * 8 + (threadIdx.x >> 5);
    int base = wid * 16;
    if (base >= N_NODES) return;
    int lane = threadIdx.x & 31;
    int end = base + 16; if (end > N_NODES) end = N_NODES;

    float4 a0 = {0,0,0,0}, a1 = {0,0,0,0}, b0 = {0,0,0,0}, b1 = {0,0,0,0};
    int cur = load_idx(batch, base);
    for (int n = base; n < end; n++) {
        int g = load_idx(batch, n);
        if (g != cur) {
            float* p = g_pool + (size_t)cur * 512 + lane * 4;
            atomicAdd(p + 0, a0.x); atomicAdd(p + 1, a0.y); atomicAdd(p + 2, a0.z); atomicAdd(p + 3, a0.w);
            atomicAdd(p + 128, a1.x); atomicAdd(p + 129, a1.y); atomicAdd(p + 130, a1.z); atomicAdd(p + 131, a1.w);
            atomicAdd(p + 256, b0.x); atomicAdd(p + 257, b0.y); atomicAdd(p + 258, b0.z); atomicAdd(p + 259, b0.w);
            atomicAdd(p + 384, b1.x); atomicAdd(p + 385, b1.y); atomicAdd(p + 386, b1.z); atomicAdd(p + 387, b1.w);
            a0 = a1 = b0 = b1 = make_float4(0,0,0,0);
            cur = g;
        }
        float4 v0, v1;
        plane_row_load(hp1, n, lane, v0, v1);
        a0.x += v0.x; a0.y += v0.y; a0.z += v0.z; a0.w += v0.w;
        a1.x += v1.x; a1.y += v1.y; a1.z += v1.z; a1.w += v1.w;
        plane_row_load(hp2, n, lane, v0, v1);
        b0.x += v0.x; b0.y += v0.y; b0.z += v0.z; b0.w += v0.w;
        b1.x += v1.x; b1.y += v1.y; b1.z += v1.z; b1.w += v1.w;
    }
    float* p = g_pool + (size_t)cur * 512 + lane * 4;
    atomicAdd(p + 0, a0.x); atomicAdd(p + 1, a0.y); atomicAdd(p + 2, a0.z); atomicAdd(p + 3, a0.w);
    atomicAdd(p + 128, a1.x); atomicAdd(p + 129, a1.y); atomicAdd(p + 130, a1.z); atomicAdd(p + 131, a1.w);
    atomicAdd(p + 256, b0.x); atomicAdd(p + 257, b0.y); atomicAdd(p + 258, b0.z); atomicAdd(p + 259, b0.w);
    atomicAdd(p + 384, b1.x); atomicAdd(p + 385, b1.y); atomicAdd(p + 386, b1.z); atomicAdd(p + 387, b1.w);
}

// ---------------- head ----------------
__global__ __launch_bounds__(256) void head_kernel(
    const float* __restrict__ W1, const float* __restrict__ b1,
    const float* __restrict__ W2, const float* __restrict__ b2,
    float* __restrict__ out)
{
    __shared__ float Ps[8][512];
    __shared__ float Hs[8][768];
    __shared__ float Os[8][10];
    int tid = threadIdx.x;
    int rowBase = blockIdx.x * 8;
    int nrows = N_GRAPHS - rowBase; if (nrows > 8) nrows = 8;

    for (int i = tid; i < 8 * 512; i += 256) {
        int r = i >> 9, c = i & 511;
        Ps[r][c] = (r < nrows) ? g_pool[(size_t)(rowBase + r) * 512 + c] : 0.f;
    }
    __syncthreads();

    for (int n = tid; n < 768; n += 256) {
        float acc[8];
#pragma unroll
        for (int r = 0; r < 8; r++) acc[r] = 0.f;
        for (int k = 0; k < 512; k++) {
            float w = W1[(size_t)k * 768 + n];
#pragma unroll
            for (int r = 0; r < 8; r++) acc[r] = fmaf(Ps[r][k], w, acc[r]);
        }
        float bb = b1[n];
#pragma unroll
        for (int r = 0; r < 8; r++) Hs[r][n] = fmaxf(acc[r] + bb, 0.f);
    }
    __syncthreads();

    if (tid < 80) {
        int r = tid / 10, c = tid % 10;
        float acc = b2[c];
        for (int k = 0; k < 768; k++) acc = fmaf(Hs[r][k], W2[(size_t)k * 10 + c], acc);
        Os[r][c] = acc;
    }
    __syncthreads();

    if (tid < nrows) {
        int r = tid;
        float mx = -1e30f;
        for (int c = 0; c < 10; c++) mx = fmaxf(mx, Os[r][c]);
        float s = 0.f;
        for (int c = 0; c < 10; c++) s += expf(Os[r][c] - mx);
        float lse = mx + logf(s);
        for (int c = 0; c < 10; c++) out[(size_t)(rowBase + r) * 10 + c] = Os[r][c] - lse;
    }
}

// ---------------- launch ----------------
extern "C" void kernel_launch(void* const* d_in, const int* in_sizes, int n_in,
                              void* d_out, int out_size) {
    const float* x     = (const float*)d_in[0];
    const void*  ei    = d_in[1];
    const void*  batch = d_in[2];
    const float* W1a = (const float*)d_in[3];
    const float* b1a = (const float*)d_in[4];
    const float* g1a = (const float*)d_in[5];
    const float* be1a= (const float*)d_in[6];
    const float* m1a = (const float*)d_in[7];
    const float* v1a = (const float*)d_in[8];
    const float* W2a = (const float*)d_in[9];
    const float* b2a = (const float*)d_in[10];
    const float* W1b = (const float*)d_in[11];
    const float* b1b = (const float*)d_in[12];
    const float* g1b = (const float*)d_in[13];
    const float* be1b= (const float*)d_in[14];
    const float* m1b = (const float*)d_in[15];
    const float* v1b = (const float*)d_in[16];
    const float* W2b = (const float*)d_in[17];
    const float* b2b = (const float*)d_in[18];
    const float* lin1W = (const float*)d_in[19];
    const float* lin1b = (const float*)d_in[20];
    const float* lin2W = (const float*)d_in[21];
    const float* lin2b = (const float*)d_in[22];
    float* out = (float*)d_out;

    unsigned char *pl0, *pl1, *hp1, *hp2, *wt;
    cudaGetSymbolAddress((void**)&pl0, g_pl0);
    cudaGetSymbolAddress((void**)&pl1, g_pl1);
    cudaGetSymbolAddress((void**)&hp1, g_hp1);
    cudaGetSymbolAddress((void**)&hp2, g_hp2);
    cudaGetSymbolAddress((void**)&wt,  g_wt);

    cudaFuncSetAttribute(gemm_mma_kernel<true, 1>,  cudaFuncAttributeMaxDynamicSharedMemorySize, GSM_BYTES);
    cudaFuncSetAttribute(gemm_mma_kernel<false, 2>, cudaFuncAttributeMaxDynamicSharedMemorySize, GSM_BYTES);

    dim3 gemmGrid(N_TILES, 2);
    const int aggGrid  = (N_NODES + 7) / 8;
    const int scanGrid = (N_NODES + 1023) / 1024; // 49

    // detect + zero counts
    detect_zero_kernel<<<(N_NODES + 255) / 256, 256>>>((const long long*)ei);

    // fused wconv + hist + pool-zero
    prep_kernel<<<WCONV_BLOCKS + HIST_BLOCKS, 256>>>(ei, W1a, W2a, W1b, W2b);

    // CSR build
    scan1_kernel<<<scanGrid, 1024>>>();
    scan3_kernel<<<scanGrid, 1024>>>(scanGrid);
    fill_kernel<<<(N_EDGES + 255) / 256, 256>>>(ei);

    // layer 1
    agg_kernel<false><<<aggGrid, 256>>>(x, nullptr, pl0);
    gemm_mma_kernel<true, 1><<<gemmGrid, 256, GSM_BYTES>>>(
        pl0, wt + 0 * 131072, b1a, g1a, be1a, m1a, v1a, pl1, N_NODES);
    gemm_mma_kernel<false, 2><<<gemmGrid, 256, GSM_BYTES>>>(
        pl1, wt + 1 * 131072, b2a, nullptr, nullptr, nullptr, nullptr, hp1, N_NODES);

    // layer 2
    agg_kernel<true><<<aggGrid, 256>>>(nullptr, hp1, pl0);
    gemm_mma_kernel<true, 1><<<gemmGrid, 256, GSM_BYTES>>>(
        pl0, wt + 2 * 131072, b1b, g1b, be1b, m1b, v1b, pl1, N_NODES);
    gemm_mma_kernel<false, 2><<<gemmGrid, 256, GSM_BYTES>>>(
        pl1, wt + 3 * 131072, b2b, nullptr, nullptr, nullptr, nullptr, hp2, N_NODES);

    // pooling (g_pool zeroed inside prep_kernel)
    pool_kernel<<<((N_NODES + 15) / 16 + 7) / 8, 256>>>(hp1, hp2, batch);

    // head
    head_kernel<<<(N_GRAPHS + 7) / 8, 256>>>(lin1W, lin1b, lin2W, lin2b, out);
}

// round 15
// speedup vs baseline: 1.1781x; 1.1781x over previous
#include <cuda_runtime.h>
#include <cuda_fp16.h>
#include <cstdint>

#define N_NODES 50000
#define N_EDGES 800000
#define DIM 256
#define N_GRAPHS 500
#define N_OUT 10
#define BN_EPS 1e-5f

#define N_TILES 391              // ceil(50000/128)
#define HTILE_BYTES 65536        // compact fp16 planes: 8 chunks * 8KB

// ---------------- scratch ----------------
__device__ unsigned char g_pl0[(size_t)N_TILES * HTILE_BYTES];
__device__ unsigned char g_pl1[(size_t)N_TILES * HTILE_BYTES];
__device__ unsigned char g_hp1[(size_t)N_TILES * HTILE_BYTES];
__device__ unsigned char g_hp2[(size_t)N_TILES * HTILE_BYTES];
__device__ float g_pool[(size_t)N_GRAPHS * 2 * DIM];
__device__ int   g_idx_is64;
__device__ int   g_counts[N_NODES];
__device__ int   g_rowptr[N_NODES + 1];
__device__ int   g_cursor[N_NODES];
__device__ int   g_esrc[N_EDGES];
__device__ int   g_partials[64];
// weights (single fp16): [slot][chunk=8][nhalf=2][8192B] = 128KB/slot
__device__ unsigned char g_wt[4 * 131072];

// ---------------- helpers ----------------
__device__ __forceinline__ uint32_t smem_u32(const void* p) {
    uint32_t a;
    asm("{ .reg .u64 t; cvta.to.shared.u64 t, %1; cvt.u32.u64 %0, t; }" : "=r"(a) : "l"(p));
    return a;
}
__device__ __forceinline__ void cp16(uint32_t s, const void* g) {
    asm volatile("cp.async.cg.shared.global [%0], [%1], 16;"
                 :: "r"(s), "l"(__cvta_generic_to_global(g)) : "memory");
}
__device__ __forceinline__ void cp_commit() { asm volatile("cp.async.commit_group;" ::: "memory"); }
__device__ __forceinline__ void ldx4(uint32_t* r, uint32_t addr) {
    asm volatile("ldmatrix.sync.aligned.m8n8.x4.shared.b16 {%0,%1,%2,%3}, [%4];"
                 : "=r"(r[0]), "=r"(r[1]), "=r"(r[2]), "=r"(r[3]) : "r"(addr));
}
__device__ __forceinline__ void ldx2(uint32_t* r, uint32_t addr) {
    asm volatile("ldmatrix.sync.aligned.m8n8.x2.shared.b16 {%0,%1}, [%2];"
                 : "=r"(r[0]), "=r"(r[1]) : "r"(addr));
}
__device__ __forceinline__ void mma16816h(float* d, const uint32_t* a, const uint32_t* b) {
    asm volatile("mma.sync.aligned.m16n8k16.row.col.f32.f16.f16.f32 "
                 "{%0,%1,%2,%3}, {%4,%5,%6,%7}, {%8,%9}, {%0,%1,%2,%3};"
                 : "+f"(d[0]), "+f"(d[1]), "+f"(d[2]), "+f"(d[3])
                 : "r"(a[0]), "r"(a[1]), "r"(a[2]), "r"(a[3]), "r"(b[0]), "r"(b[1]));
}
__device__ __forceinline__ uint32_t tswz(int r, int ccol) {
    int rr = r >> 1;
    return ((uint32_t)rr << 7) + ((uint32_t)((ccol + ((r & 1) << 2)) ^ (rr & 7)) << 4);
}
__device__ __forceinline__ uint32_t packhf2(float a, float b) {
    __half2 h = __floats2half2_rn(a, b);
    return *(uint32_t*)&h;
}
__device__ __forceinline__ void plane_row_load(const unsigned char* P, int s, int lane,
                                               float4& v0, float4& v1) {
    int tile = s >> 7, r = s & 127;
    int ccol = (lane >> 1) & 3, c0 = lane >> 3;
    uint32_t off = tswz(r, ccol) + (uint32_t)(lane & 1) * 8;
    const unsigned char* base = P + (size_t)tile * HTILE_BYTES;
    uint2 u0 = *(const uint2*)(base + (size_t)c0 * 8192 + off);
    uint2 u1 = *(const uint2*)(base + (size_t)(c0 + 4) * 8192 + off);
    float2 f;
    f = __half22float2(*(__half2*)&u0.x); v0.x = f.x; v0.y = f.y;
    f = __half22float2(*(__half2*)&u0.y); v0.z = f.x; v0.w = f.y;
    f = __half22float2(*(__half2*)&u1.x); v1.x = f.x; v1.y = f.y;
    f = __half22float2(*(__half2*)&u1.y); v1.z = f.x; v1.w = f.y;
}

// ---------------- dtype detection ----------------
__device__ __forceinline__ int load_idx(const void* p, int i) {
    if (g_idx_is64) return (int)((const long long*)p)[i];
    return ((const int*)p)[i];
}

// ---------------- detect + zero counts (fused) ----------------
__global__ void detect_zero_kernel(const long long* __restrict__ ei) {
    int i = blockIdx.x * blockDim.x + threadIdx.x;
    if (i < N_NODES) g_counts[i] = 0;
    if (i == 0) {
        int ok = 1;
        for (int j = 0; j < 64; j++) {
            long long v = ei[j];
            if (v < 0 || v >= N_NODES) ok = 0;
        }
        g_idx_is64 = ok;
    }
}

// ---------------- fused weight-conv + histogram + pool-zero ----------------
#define WCONV_BLOCKS 1024
#define HIST_BLOCKS  3125
__global__ void prep_kernel(const void* __restrict__ ei,
                            const float* __restrict__ Wa, const float* __restrict__ Wb,
                            const float* __restrict__ Wc, const float* __restrict__ Wd) {
    int b = blockIdx.x;
    if (b < WCONV_BLOCKS) {
        int slot = b >> 8;
        const float* W = (slot == 0) ? Wa : (slot == 1) ? Wb : (slot == 2) ? Wc : Wd;
        int id = (b & 255) * 256 + threadIdx.x;
        int k = id >> 8, n = id & 255;
        float v = W[(size_t)k * 256 + n];
        int c = k >> 5, kl = k & 31, h = n >> 7, r = n & 127;
        uint32_t off = tswz(r, kl >> 3) + (uint32_t)(kl & 7) * 2;
        size_t base = (size_t)slot * 131072 + (size_t)c * 16384 + (size_t)h * 8192;
        *(__half*)(g_wt + base + off) = __float2half_rn(v);
    } else {
        int e = (b - WCONV_BLOCKS) * 256 + threadIdx.x;
        if (e < N_GRAPHS * 2 * DIM) g_pool[e] = 0.f;
        if (e >= N_EDGES) return;
        atomicAdd(&g_counts[load_idx(ei, N_EDGES + e)], 1);
    }
}

__global__ void scan1_kernel() {
    __shared__ int wsum[32];
    int tid = threadIdx.x;
    int i = blockIdx.x * 1024 + tid;
    int v = (i < N_NODES) ? g_counts[i] : 0;
    int s = v;
    int lane = tid & 31;
#pragma unroll
    for (int o = 1; o < 32; o <<= 1) {
        int t = __shfl_up_sync(0xffffffffu, s, o);
        if (lane >= o) s += t;
    }
    if (lane == 31) wsum[tid >> 5] = s;
    __syncthreads();
    if (tid < 32) {
        int ws = wsum[tid];
#pragma unroll
        for (int o = 1; o < 32; o <<= 1) {
            int t = __shfl_up_sync(0xffffffffu, ws, o);
            if (tid >= o) ws += t;
        }
        wsum[tid] = ws;
    }
    __syncthreads();
    int off = (tid >= 32) ? wsum[(tid >> 5) - 1] : 0;
    int incl = s + off;
    if (i < N_NODES) g_rowptr[i] = incl - v;
    if (tid == 1023) g_partials[blockIdx.x] = incl;
}
__global__ void scan3_kernel(int nblk) {
    __shared__ int soff;
    int tid = threadIdx.x;
    if (tid < 32) {
        int acc = 0;
        int j0 = tid, j1 = tid + 32;
        if (j0 < nblk && j0 < blockIdx.x) acc += g_partials[j0];
        if (j1 < nblk && j1 < blockIdx.x) acc += g_partials[j1];
#pragma unroll
        for (int o = 16; o > 0; o >>= 1) acc += __shfl_down_sync(0xffffffffu, acc, o);
        if (tid == 0) soff = acc;
    }
    __syncthreads();
    int i = blockIdx.x * 1024 + tid;
    if (i < N_NODES) {
        int r = g_rowptr[i] + soff;
        g_rowptr[i] = r;
        g_cursor[i] = r;
    }
    if (i == 0) g_rowptr[N_NODES] = N_EDGES;
}
__global__ void fill_kernel(const void* __restrict__ ei) {
    int e = blockIdx.x * blockDim.x + threadIdx.x;
    if (e >= N_EDGES) return;
    int s = load_idx(ei, e);
    int d = load_idx(ei, N_EDGES + e);
    g_esrc[atomicAdd(&g_cursor[d], 1)] = s;
}

// ---------------- gather aggregation -> compact fp16 plane ----------------
template <bool IN_PLANES>
__global__ __launch_bounds__(256) void agg_kernel(const float* __restrict__ x,
                                                  const unsigned char* __restrict__ Ip,
                                                  unsigned char* __restrict__ Op) {
    int node = blockIdx.x * 8 + (threadIdx.x >> 5);
    if (node >= N_NODES) return;
    int lane = threadIdx.x & 31;
    const float4* xv = (const float4*)x;
    float4 acc0, acc1;
    if (IN_PLANES) {
        plane_row_load(Ip, node, lane, acc0, acc1);
    } else {
        acc0 = xv[(size_t)node * 64 + lane];
        acc1 = xv[(size_t)node * 64 + 32 + lane];
    }
    int start = g_rowptr[node];
    int end   = g_rowptr[node + 1];
    int k = start;
    for (; k + 1 < end; k += 2) {
        int sa = g_esrc[k];
        int sb = g_esrc[k + 1];
        float4 a0, a1, b0, b1;
        if (IN_PLANES) {
            plane_row_load(Ip, sa, lane, a0, a1);
            plane_row_load(Ip, sb, lane, b0, b1);
        } else {
            const float4* xa = xv + (size_t)sa * 64;
            const float4* xb = xv + (size_t)sb * 64;
            a0 = xa[lane]; a1 = xa[lane + 32];
            b0 = xb[lane]; b1 = xb[lane + 32];
        }
        acc0.x += a0.x + b0.x; acc0.y += a0.y + b0.y;
        acc0.z += a0.z + b0.z; acc0.w += a0.w + b0.w;
        acc1.x += a1.x + b1.x; acc1.y += a1.y + b1.y;
        acc1.z += a1.z + b1.z; acc1.w += a1.w + b1.w;
    }
    if (k < end) {
        int sa = g_esrc[k];
        float4 a0, a1;
        if (IN_PLANES) {
            plane_row_load(Ip, sa, lane, a0, a1);
        } else {
            const float4* xa = xv + (size_t)sa * 64;
            a0 = xa[lane]; a1 = xa[lane + 32];
        }
        acc0.x += a0.x; acc0.y += a0.y; acc0.z += a0.z; acc0.w += a0.w;
        acc1.x += a1.x; acc1.y += a1.y; acc1.z += a1.z; acc1.w += a1.w;
    }
    int tile = node >> 7, r = node & 127;
    int ccol = (lane >> 1) & 3;
    int c0 = lane >> 3;
    uint32_t off = tswz(r, ccol) + (uint32_t)(lane & 1) * 8;
    unsigned char* base = Op + (size_t)tile * HTILE_BYTES;
    *(uint2*)(base + (size_t)c0 * 8192 + off) =
        make_uint2(packhf2(acc0.x, acc0.y), packhf2(acc0.z, acc0.w));
    *(uint2*)(base + (size_t)(c0 + 4) * 8192 + off) =
        make_uint2(packhf2(acc1.x, acc1.y), packhf2(acc1.z, acc1.w));
}

// ---------------- single-pass fp16 tensor-core GEMM ----------------
// grid (N_TILES, 2), 256 threads, 2 CTAs/SM. Stage = A(8KB) + B(8KB) = 16KB, x2.
#define STAGE_BYTES 16384
#define GSM_BYTES (2 * STAGE_BYTES + 1024)

template <bool DO_BN>
__global__ __launch_bounds__(256, 2) void gemm_mma_kernel(
    const unsigned char* __restrict__ Ap, const unsigned char* __restrict__ Wslot,
    const float* __restrict__ bias,
    const float* __restrict__ gamma, const float* __restrict__ beta,
    const float* __restrict__ mean,  const float* __restrict__ var,
    unsigned char* __restrict__ Oplanes, int M)
{
    extern __shared__ char dsm[];
    uint32_t sb0 = smem_u32(dsm);
    uint32_t sb = (sb0 + 1023u) & ~1023u;

    const int tid = threadIdx.x, wid = tid >> 5, lane = tid & 31;
    const int rowBase = blockIdx.x * 128;
    const int nh = blockIdx.y;
    const int wm = (wid >> 2) * 64;
    const int wn = (wid & 3) * 32;

    const int lr = lane & 7;
    const int ag = lane >> 3;
    const int aRowOff = (ag & 1) * 8 + lr;
    const int aCc = ag >> 1;
    const int bCc = (lane >> 3) & 1;

    uint32_t aBase[4], bBase[4];
    int aXor[4], aS4[4], bXor[4], bS4[4];
#pragma unroll
    for (int mi = 0; mi < 4; mi++) {
        int r = wm + mi * 16 + aRowOff;
        aBase[mi] = (uint32_t)(r >> 1) << 7;
        aXor[mi] = (r >> 1) & 7;
        aS4[mi] = (r & 1) << 2;
    }
#pragma unroll
    for (int ni = 0; ni < 4; ni++) {
        int r = wn + ni * 8 + lr;
        bBase[ni] = (uint32_t)(r >> 1) << 7;
        bXor[ni] = (r >> 1) & 7;
        bS4[ni] = (r & 1) << 2;
    }

    float acc[4][4][4];
#pragma unroll
    for (int mi = 0; mi < 4; mi++)
#pragma unroll
        for (int ni = 0; ni < 4; ni++)
#pragma unroll
            for (int q = 0; q < 4; q++) acc[mi][ni][q] = 0.f;

    const unsigned char* Asrc = Ap + (size_t)blockIdx.x * HTILE_BYTES;
    const unsigned char* Bsrc0 = Wslot + (size_t)nh * 8192;

    // prefetch chunk 0 (A: 512 x 16B, B: 512 x 16B)
    {
#pragma unroll
        for (int j = 0; j < 2; j++) {
            int idx = tid + j * 256;
            cp16(sb + idx * 16, Asrc + idx * 16);
            cp16(sb + 8192 + idx * 16, Bsrc0 + idx * 16);
        }
        cp_commit();
    }

    for (int c = 0; c < 8; c++) {
        int p = c & 1;
        if (c < 7) {
            uint32_t sB = sb + (p ^ 1) * STAGE_BYTES;
            const unsigned char* ga = Asrc + (size_t)(c + 1) * 8192;
            const unsigned char* gb = Bsrc0 + (size_t)(c + 1) * 16384;
#pragma unroll
            for (int j = 0; j < 2; j++) {
                int idx = tid + j * 256;
                cp16(sB + idx * 16, ga + idx * 16);
                cp16(sB + 8192 + idx * 16, gb + idx * 16);
            }
            cp_commit();
            asm volatile("cp.async.wait_group 1;" ::: "memory");
        } else {
            asm volatile("cp.async.wait_group 0;" ::: "memory");
        }
        __syncthreads();

        uint32_t bufb = sb + p * STAGE_BYTES;
        uint32_t sA = bufb;
        uint32_t sB = bufb + 8192;

#pragma unroll
        for (int ks = 0; ks < 2; ks++) {
            int ka = ks * 2 + aCc;
            int kb = ks * 2 + bCc;
            uint32_t ah[4][4];
#pragma unroll
            for (int mi = 0; mi < 4; mi++)
                ldx4(ah[mi], sA + aBase[mi] + ((uint32_t)((ka + aS4[mi]) ^ aXor[mi]) << 4));
            uint32_t b[4][2];
#pragma unroll
            for (int ni = 0; ni < 4; ni++)
                ldx2(b[ni], sB + bBase[ni] + ((uint32_t)((kb + bS4[ni]) ^ bXor[ni]) << 4));
#pragma unroll
            for (int mi = 0; mi < 4; mi++)
#pragma unroll
                for (int ni = 0; ni < 4; ni++) mma16816h(acc[mi][ni], ah[mi], b[ni]);
        }
        __syncthreads();
    }

    // ---- epilogue: write compact fp16 plane ----
    float sc[4][2], sh[4][2];
#pragma unroll
    for (int ni = 0; ni < 4; ni++) {
#pragma unroll
        for (int j = 0; j < 2; j++) {
            int col = nh * 128 + wn + ni * 8 + (lane & 3) * 2 + j;
            float bv = bias[col];
            if (DO_BN) {
                float s = gamma[col] * rsqrtf(var[col] + BN_EPS);
                sc[ni][j] = s;
                sh[ni][j] = beta[col] - mean[col] * s + bv * s;
            } else {
                sc[ni][j] = 1.f;
                sh[ni][j] = bv;
            }
        }
    }
#pragma unroll
    for (int mi = 0; mi < 4; mi++) {
        int rl0 = wm + mi * 16 + (lane >> 2);
        int rl1 = rl0 + 8;
#pragma unroll
        for (int ni = 0; ni < 4; ni++) {
            int c0g = nh * 128 + wn + ni * 8 + (lane & 3) * 2;
            float v0 = fmaxf(acc[mi][ni][0] * sc[ni][0] + sh[ni][0], 0.f);
            float v1 = fmaxf(acc[mi][ni][1] * sc[ni][1] + sh[ni][1], 0.f);
            float v2 = fmaxf(acc[mi][ni][2] * sc[ni][0] + sh[ni][0], 0.f);
            float v3 = fmaxf(acc[mi][ni][3] * sc[ni][1] + sh[ni][1], 0.f);
            int ch = c0g >> 5, kl = c0g & 31;
            uint32_t bib = (uint32_t)(kl & 7) * 2;
            unsigned char* tb = Oplanes + (size_t)blockIdx.x * HTILE_BYTES + (size_t)ch * 8192;
            if (rowBase + rl0 < M)
                *(uint32_t*)(tb + tswz(rl0, kl >> 3) + bib) = packhf2(v0, v1);
            if (rowBase + rl1 < M)
                *(uint32_t*)(tb + tswz(rl1, kl >> 3) + bib) = packhf2(v2, v3);
        }
    }
}

// ---------------- pooling (reads compact fp16 planes) ----------------
__global__ void pool_kernel(const unsigned char* __restrict__ hp1,
                            const unsigned char* __restrict__ hp2,
                            const void* __restrict__ batch) {
    int wid = blockIdx.x * 8 + (threadIdx.x >> 5);
    int base = wid * 16;
    if (base >= N_NODES) return;
    int lane = threadIdx.x & 31;
    int end = base + 16; if (end > N_NODES) end = N_NODES;

    float4 a0 = {0,0,0,0}, a1 = {0,0,0,0}, b0 = {0,0,0,0}, b1 = {0,0,0,0};
    int cur = load_idx(batch, base);
    for (int n = base; n < end; n++) {
        int g = load_idx(batch, n);
        if (g != cur) {
            float* p = g_pool + (size_t)cur * 512 + lane * 4;
            atomicAdd(p + 0, a0.x); atomicAdd(p + 1, a0.y); atomicAdd(p + 2, a0.z); atomicAdd(p + 3, a0.w);
            atomicAdd(p + 128, a1.x); atomicAdd(p + 129, a1.y); atomicAdd(p + 130, a1.z); atomicAdd(p + 131, a1.w);
            atomicAdd(p + 256, b0.x); atomicAdd(p + 257, b0.y); atomicAdd(p + 258, b0.z); atomicAdd(p + 259, b0.w);
            atomicAdd(p + 384, b1.x); atomicAdd(p + 385, b1.y); atomicAdd(p + 386, b1.z); atomicAdd(p + 387, b1.w);
            a0 = a1 = b0 = b1 = make_float4(0,0,0,0);
            cur = g;
        }
        float4 v0, v1;
        plane_row_load(hp1, n, lane, v0, v1);
        a0.x += v0.x; a0.y += v0.y; a0.z += v0.z; a0.w += v0.w;
        a1.x += v1.x; a1.y += v1.y; a1.z += v1.z; a1.w += v1.w;
        plane_row_load(hp2, n, lane, v0, v1);
        b0.x += v0.x; b0.y += v0.y; b0.z += v0.z; b0.w += v0.w;
        b1.x += v1.x; b1.y += v1.y; b1.z += v1.z; b1.w += v1.w;
    }
    float* p = g_pool + (size_t)cur * 512 + lane * 4;
    atomicAdd(p + 0, a0.x); atomicAdd(p + 1, a0.y); atomicAdd(p + 2, a0.z); atomicAdd(p + 3, a0.w);
    atomicAdd(p + 128, a1.x); atomicAdd(p + 129, a1.y); atomicAdd(p + 130, a1.z); atomicAdd(p + 131, a1.w);
    atomicAdd(p + 256, b0.x); atomicAdd(p + 257, b0.y); atomicAdd(p + 258, b0.z); atomicAdd(p + 259, b0.w);
    atomicAdd(p + 384, b1.x); atomicAdd(p + 385, b1.y); atomicAdd(p + 386, b1.z); atomicAdd(p + 387, b1.w);
}

// ---------------- head ----------------
__global__ __launch_bounds__(256) void head_kernel(
    const float* __restrict__ W1, const float* __restrict__ b1,
    const float* __restrict__ W2, const float* __restrict__ b2,
    float* __restrict__ out)
{
    __shared__ float Ps[8][512];
    __shared__ float Hs[8][768];
    __shared__ float Os[8][10];
    int tid = threadIdx.x;
    int rowBase = blockIdx.x * 8;
    int nrows = N_GRAPHS - rowBase; if (nrows > 8) nrows = 8;

    for (int i = tid; i < 8 * 512; i += 256) {
        int r = i >> 9, c = i & 511;
        Ps[r][c] = (r < nrows) ? g_pool[(size_t)(rowBase + r) * 512 + c] : 0.f;
    }
    __syncthreads();

    for (int n = tid; n < 768; n += 256) {
        float acc[8];
#pragma unroll
        for (int r = 0; r < 8; r++) acc[r] = 0.f;
        for (int k = 0; k < 512; k++) {
            float w = W1[(size_t)k * 768 + n];
#pragma unroll
            for (int r = 0; r < 8; r++) acc[r] = fmaf(Ps[r][k], w, acc[r]);
        }
        float bb = b1[n];
#pragma unroll
        for (int r = 0; r < 8; r++) Hs[r][n] = fmaxf(acc[r] + bb, 0.f);
    }
    __syncthreads();

    if (tid < 80) {
        int r = tid / 10, c = tid % 10;
        float acc = b2[c];
        for (int k = 0; k < 768; k++) acc = fmaf(Hs[r][k], W2[(size_t)k * 10 + c], acc);
        Os[r][c] = acc;
    }
    __syncthreads();

    if (tid < nrows) {
        int r = tid;
        float mx = -1e30f;
        for (int c = 0; c < 10; c++) mx = fmaxf(mx, Os[r][c]);
        float s = 0.f;
        for (int c = 0; c < 10; c++) s += expf(Os[r][c] - mx);
        float lse = mx + logf(s);
        for (int c = 0; c < 10; c++) out[(size_t)(rowBase + r) * 10 + c] = Os[r][c] - lse;
    }
}

// ---------------- launch ----------------
extern "C" void kernel_launch(void* const* d_in, const int* in_sizes, int n_in,
                              void* d_out, int out_size) {
    const float* x     = (const float*)d_in[0];
    const void*  ei    = d_in[1];
    const void*  batch = d_in[2];
    const float* W1a = (const float*)d_in[3];
    const float* b1a = (const float*)d_in[4];
    const float* g1a = (const float*)d_in[5];
    const float* be1a= (const float*)d_in[6];
    const float* m1a = (const float*)d_in[7];
    const float* v1a = (const float*)d_in[8];
    const float* W2a = (const float*)d_in[9];
    const float* b2a = (const float*)d_in[10];
    const float* W1b = (const float*)d_in[11];
    const float* b1b = (const float*)d_in[12];
    const float* g1b = (const float*)d_in[13];
    const float* be1b= (const float*)d_in[14];
    const float* m1b = (const float*)d_in[15];
    const float* v1b = (const float*)d_in[16];
    const float* W2b = (const float*)d_in[17];
    const float* b2b = (const float*)d_in[18];
    const float* lin1W = (const float*)d_in[19];
    const float* lin1b = (const float*)d_in[20];
    const float* lin2W = (const float*)d_in[21];
    const float* lin2b = (const float*)d_in[22];
    float* out = (float*)d_out;

    unsigned char *pl0, *pl1, *hp1, *hp2, *wt;
    cudaGetSymbolAddress((void**)&pl0, g_pl0);
    cudaGetSymbolAddress((void**)&pl1, g_pl1);
    cudaGetSymbolAddress((void**)&hp1, g_hp1);
    cudaGetSymbolAddress((void**)&hp2, g_hp2);
    cudaGetSymbolAddress((void**)&wt,  g_wt);

    cudaFuncSetAttribute(gemm_mma_kernel<true>,  cudaFuncAttributeMaxDynamicSharedMemorySize, GSM_BYTES);
    cudaFuncSetAttribute(gemm_mma_kernel<false>, cudaFuncAttributeMaxDynamicSharedMemorySize, GSM_BYTES);

    dim3 gemmGrid(N_TILES, 2);
    const int aggGrid  = (N_NODES + 7) / 8;
    const int scanGrid = (N_NODES + 1023) / 1024; // 49

    // detect + zero counts
    detect_zero_kernel<<<(N_NODES + 255) / 256, 256>>>((const long long*)ei);

    // fused wconv + hist + pool-zero
    prep_kernel<<<WCONV_BLOCKS + HIST_BLOCKS, 256>>>(ei, W1a, W2a, W1b, W2b);

    // CSR build
    scan1_kernel<<<scanGrid, 1024>>>();
    scan3_kernel<<<scanGrid, 1024>>>(scanGrid);
    fill_kernel<<<(N_EDGES + 255) / 256, 256>>>(ei);

    // layer 1
    agg_kernel<false><<<aggGrid, 256>>>(x, nullptr, pl0);
    gemm_mma_kernel<true ><<<gemmGrid, 256, GSM_BYTES>>>(
        pl0, wt + 0 * 131072, b1a, g1a, be1a, m1a, v1a, pl1, N_NODES);
    gemm_mma_kernel<false><<<gemmGrid, 256, GSM_BYTES>>>(
        pl1, wt + 1 * 131072, b2a, nullptr, nullptr, nullptr, nullptr, hp1, N_NODES);

    // layer 2
    agg_kernel<true><<<aggGrid, 256>>>(nullptr, hp1, pl0);
    gemm_mma_kernel<true ><<<gemmGrid, 256, GSM_BYTES>>>(
        pl0, wt + 2 * 131072, b1b, g1b, be1b, m1b, v1b, pl1, N_NODES);
    gemm_mma_kernel<false><<<gemmGrid, 256, GSM_BYTES>>>(
        pl1, wt + 3 * 131072, b2b, nullptr, nullptr, nullptr, nullptr, hp2, N_NODES);

    // pooling (g_pool zeroed inside prep_kernel)
    pool_kernel<<<((N_NODES + 15) / 16 + 7) / 8, 256>>>(hp1, hp2, batch);

    // head
    head_kernel<<<(N_GRAPHS + 7) / 8, 256>>>(lin1W, lin1b, lin2W, lin2b, out);
}

// round 16
// speedup vs baseline: 1.2030x; 1.0211x over previous
#include <cuda_runtime.h>
#include <cuda_fp16.h>
#include <cstdint>

#define N_NODES 50000
#define N_EDGES 800000
#define DIM 256
#define N_GRAPHS 500
#define N_OUT 10
#define BN_EPS 1e-5f

#define N_TILES 391              // ceil(50000/128)
#define HTILE_BYTES 65536        // compact fp16 planes: 8 chunks * 8KB

// ---------------- scratch ----------------
__device__ unsigned char g_px [(size_t)N_TILES * HTILE_BYTES];
__device__ unsigned char g_pl0[(size_t)N_TILES * HTILE_BYTES];
__device__ unsigned char g_pl1[(size_t)N_TILES * HTILE_BYTES];
__device__ unsigned char g_hp1[(size_t)N_TILES * HTILE_BYTES];
__device__ unsigned char g_hp2[(size_t)N_TILES * HTILE_BYTES];
__device__ float g_pool[(size_t)N_GRAPHS * 2 * DIM];
__device__ int   g_idx_is64;
__device__ int   g_counts[N_NODES];
__device__ int   g_rowptr[N_NODES + 1];
__device__ int   g_cursor[N_NODES];
__device__ int   g_esrc[N_EDGES];
__device__ int   g_partials[64];
// weights (single fp16): [slot][chunk=8][nhalf=2][8192B] = 128KB/slot
__device__ unsigned char g_wt[4 * 131072];

// ---------------- helpers ----------------
__device__ __forceinline__ uint32_t smem_u32(const void* p) {
    uint32_t a;
    asm("{ .reg .u64 t; cvta.to.shared.u64 t, %1; cvt.u32.u64 %0, t; }" : "=r"(a) : "l"(p));
    return a;
}
__device__ __forceinline__ void cp16(uint32_t s, const void* g) {
    asm volatile("cp.async.cg.shared.global [%0], [%1], 16;"
                 :: "r"(s), "l"(__cvta_generic_to_global(g)) : "memory");
}
__device__ __forceinline__ void cp_commit() { asm volatile("cp.async.commit_group;" ::: "memory"); }
__device__ __forceinline__ void ldx4(uint32_t* r, uint32_t addr) {
    asm volatile("ldmatrix.sync.aligned.m8n8.x4.shared.b16 {%0,%1,%2,%3}, [%4];"
                 : "=r"(r[0]), "=r"(r[1]), "=r"(r[2]), "=r"(r[3]) : "r"(addr));
}
__device__ __forceinline__ void ldx2(uint32_t* r, uint32_t addr) {
    asm volatile("ldmatrix.sync.aligned.m8n8.x2.shared.b16 {%0,%1}, [%2];"
                 : "=r"(r[0]), "=r"(r[1]) : "r"(addr));
}
__device__ __forceinline__ void mma16816h(float* d, const uint32_t* a, const uint32_t* b) {
    asm volatile("mma.sync.aligned.m16n8k16.row.col.f32.f16.f16.f32 "
                 "{%0,%1,%2,%3}, {%4,%5,%6,%7}, {%8,%9}, {%0,%1,%2,%3};"
                 : "+f"(d[0]), "+f"(d[1]), "+f"(d[2]), "+f"(d[3])
                 : "r"(a[0]), "r"(a[1]), "r"(a[2]), "r"(a[3]), "r"(b[0]), "r"(b[1]));
}
__device__ __forceinline__ uint32_t tswz(int r, int ccol) {
    int rr = r >> 1;
    return ((uint32_t)rr << 7) + ((uint32_t)((ccol + ((r & 1) << 2)) ^ (rr & 7)) << 4);
}
__device__ __forceinline__ uint32_t packhf2(float a, float b) {
    __half2 h = __floats2half2_rn(a, b);
    return *(uint32_t*)&h;
}
__device__ __forceinline__ void plane_row_load(const unsigned char* P, int s, int lane,
                                               float4& v0, float4& v1) {
    int tile = s >> 7, r = s & 127;
    int ccol = (lane >> 1) & 3, c0 = lane >> 3;
    uint32_t off = tswz(r, ccol) + (uint32_t)(lane & 1) * 8;
    const unsigned char* base = P + (size_t)tile * HTILE_BYTES;
    uint2 u0 = *(const uint2*)(base + (size_t)c0 * 8192 + off);
    uint2 u1 = *(const uint2*)(base + (size_t)(c0 + 4) * 8192 + off);
    float2 f;
    f = __half22float2(*(__half2*)&u0.x); v0.x = f.x; v0.y = f.y;
    f = __half22float2(*(__half2*)&u0.y); v0.z = f.x; v0.w = f.y;
    f = __half22float2(*(__half2*)&u1.x); v1.x = f.x; v1.y = f.y;
    f = __half22float2(*(__half2*)&u1.y); v1.z = f.x; v1.w = f.y;
}
__device__ __forceinline__ void plane_row_store(unsigned char* P, int node, int lane,
                                                const float4& a0, const float4& a1) {
    int tile = node >> 7, r = node & 127;
    int ccol = (lane >> 1) & 3, c0 = lane >> 3;
    uint32_t off = tswz(r, ccol) + (uint32_t)(lane & 1) * 8;
    unsigned char* base = P + (size_t)tile * HTILE_BYTES;
    *(uint2*)(base + (size_t)c0 * 8192 + off) =
        make_uint2(packhf2(a0.x, a0.y), packhf2(a0.z, a0.w));
    *(uint2*)(base + (size_t)(c0 + 4) * 8192 + off) =
        make_uint2(packhf2(a1.x, a1.y), packhf2(a1.z, a1.w));
}

// ---------------- dtype detection ----------------
__device__ __forceinline__ int load_idx(const void* p, int i) {
    if (g_idx_is64) return (int)((const long long*)p)[i];
    return ((const int*)p)[i];
}

// ---------------- detect + zero counts (fused) ----------------
__global__ void detect_zero_kernel(const long long* __restrict__ ei) {
    int i = blockIdx.x * blockDim.x + threadIdx.x;
    if (i < N_NODES) g_counts[i] = 0;
    if (i == 0) {
        int ok = 1;
        for (int j = 0; j < 64; j++) {
            long long v = ei[j];
            if (v < 0 || v >= N_NODES) ok = 0;
        }
        g_idx_is64 = ok;
    }
}

// ---------------- fused weight-conv + x-conv + histogram + pool-zero ----------------
#define WCONV_BLOCKS 1024
#define HIST_BLOCKS  3125
#define XCONV_BLOCKS 6250        // 8 warps/block, 1 node/warp
__global__ void prep_kernel(const void* __restrict__ ei, const float* __restrict__ x,
                            const float* __restrict__ Wa, const float* __restrict__ Wb,
                            const float* __restrict__ Wc, const float* __restrict__ Wd) {
    int b = blockIdx.x;
    if (b < WCONV_BLOCKS) {
        int slot = b >> 8;
        const float* W = (slot == 0) ? Wa : (slot == 1) ? Wb : (slot == 2) ? Wc : Wd;
        int id = (b & 255) * 256 + threadIdx.x;
        int k = id >> 8, n = id & 255;
        float v = W[(size_t)k * 256 + n];
        int c = k >> 5, kl = k & 31, h = n >> 7, r = n & 127;
        uint32_t off = tswz(r, kl >> 3) + (uint32_t)(kl & 7) * 2;
        size_t base = (size_t)slot * 131072 + (size_t)c * 16384 + (size_t)h * 8192;
        *(__half*)(g_wt + base + off) = __float2half_rn(v);
    } else if (b < WCONV_BLOCKS + HIST_BLOCKS) {
        int e = (b - WCONV_BLOCKS) * 256 + threadIdx.x;
        if (e < N_GRAPHS * 2 * DIM) g_pool[e] = 0.f;
        if (e >= N_EDGES) return;
        atomicAdd(&g_counts[load_idx(ei, N_EDGES + e)], 1);
    } else {
        int node = (b - WCONV_BLOCKS - HIST_BLOCKS) * 8 + (threadIdx.x >> 5);
        if (node >= N_NODES) return;
        int lane = threadIdx.x & 31;
        const float4* xv = (const float4*)x;
        float4 a0 = xv[(size_t)node * 64 + lane];
        float4 a1 = xv[(size_t)node * 64 + 32 + lane];
        plane_row_store(g_px, node, lane, a0, a1);
    }
}

__global__ void scan1_kernel() {
    __shared__ int wsum[32];
    int tid = threadIdx.x;
    int i = blockIdx.x * 1024 + tid;
    int v = (i < N_NODES) ? g_counts[i] : 0;
    int s = v;
    int lane = tid & 31;
#pragma unroll
    for (int o = 1; o < 32; o <<= 1) {
        int t = __shfl_up_sync(0xffffffffu, s, o);
        if (lane >= o) s += t;
    }
    if (lane == 31) wsum[tid >> 5] = s;
    __syncthreads();
    if (tid < 32) {
        int ws = wsum[tid];
#pragma unroll
        for (int o = 1; o < 32; o <<= 1) {
            int t = __shfl_up_sync(0xffffffffu, ws, o);
            if (tid >= o) ws += t;
        }
        wsum[tid] = ws;
    }
    __syncthreads();
    int off = (tid >= 32) ? wsum[(tid >> 5) - 1] : 0;
    int incl = s + off;
    if (i < N_NODES) g_rowptr[i] = incl - v;
    if (tid == 1023) g_partials[blockIdx.x] = incl;
}
__global__ void scan3_kernel(int nblk) {
    __shared__ int soff;
    int tid = threadIdx.x;
    if (tid < 32) {
        int acc = 0;
        int j0 = tid, j1 = tid + 32;
        if (j0 < nblk && j0 < blockIdx.x) acc += g_partials[j0];
        if (j1 < nblk && j1 < blockIdx.x) acc += g_partials[j1];
#pragma unroll
        for (int o = 16; o > 0; o >>= 1) acc += __shfl_down_sync(0xffffffffu, acc, o);
        if (tid == 0) soff = acc;
    }
    __syncthreads();
    int i = blockIdx.x * 1024 + tid;
    if (i < N_NODES) {
        int r = g_rowptr[i] + soff;
        g_rowptr[i] = r;
        g_cursor[i] = r;
    }
    if (i == 0) g_rowptr[N_NODES] = N_EDGES;
}
__global__ void fill_kernel(const void* __restrict__ ei) {
    int e = blockIdx.x * blockDim.x + threadIdx.x;
    if (e >= N_EDGES) return;
    int s = load_idx(ei, e);
    int d = load_idx(ei, N_EDGES + e);
    g_esrc[atomicAdd(&g_cursor[d], 1)] = s;
}

// ---------------- gather aggregation (plane -> plane), 2-way unroll ----------------
__global__ __launch_bounds__(256) void agg_kernel(const unsigned char* __restrict__ Ip,
                                                  unsigned char* __restrict__ Op) {
    int node = blockIdx.x * 8 + (threadIdx.x >> 5);
    if (node >= N_NODES) return;
    int lane = threadIdx.x & 31;
    float4 acc0, acc1;
    plane_row_load(Ip, node, lane, acc0, acc1);
    int start = g_rowptr[node];
    int end   = g_rowptr[node + 1];
    int k = start;
    for (; k + 1 < end; k += 2) {
        int sa = g_esrc[k];
        int sb = g_esrc[k + 1];
        float4 a0, a1, b0, b1;
        plane_row_load(Ip, sa, lane, a0, a1);
        plane_row_load(Ip, sb, lane, b0, b1);
        acc0.x += a0.x + b0.x; acc0.y += a0.y + b0.y;
        acc0.z += a0.z + b0.z; acc0.w += a0.w + b0.w;
        acc1.x += a1.x + b1.x; acc1.y += a1.y + b1.y;
        acc1.z += a1.z + b1.z; acc1.w += a1.w + b1.w;
    }
    if (k < end) {
        int sa = g_esrc[k];
        float4 a0, a1;
        plane_row_load(Ip, sa, lane, a0, a1);
        acc0.x += a0.x; acc0.y += a0.y; acc0.z += a0.z; acc0.w += a0.w;
        acc1.x += a1.x; acc1.y += a1.y; acc1.z += a1.z; acc1.w += a1.w;
    }
    plane_row_store(Op, node, lane, acc0, acc1);
}

// ---------------- single-pass fp16 tensor-core GEMM ----------------
// grid (N_TILES, 2), 256 threads, 2 CTAs/SM. Stage = A(8KB) + B(8KB) = 16KB, x2.
#define STAGE_BYTES 16384
#define GSM_BYTES (2 * STAGE_BYTES + 1024)

template <bool DO_BN>
__global__ __launch_bounds__(256, 2) void gemm_mma_kernel(
    const unsigned char* __restrict__ Ap, const unsigned char* __restrict__ Wslot,
    const float* __restrict__ bias,
    const float* __restrict__ gamma, const float* __restrict__ beta,
    const float* __restrict__ mean,  const float* __restrict__ var,
    unsigned char* __restrict__ Oplanes, int M)
{
    extern __shared__ char dsm[];
    uint32_t sb0 = smem_u32(dsm);
    uint32_t sb = (sb0 + 1023u) & ~1023u;

    const int tid = threadIdx.x, wid = tid >> 5, lane = tid & 31;
    const int rowBase = blockIdx.x * 128;
    const int nh = blockIdx.y;
    const int wm = (wid >> 2) * 64;
    const int wn = (wid & 3) * 32;

    const int lr = lane & 7;
    const int ag = lane >> 3;
    const int aRowOff = (ag & 1) * 8 + lr;
    const int aCc = ag >> 1;
    const int bCc = (lane >> 3) & 1;

    uint32_t aBase[4], bBase[4];
    int aXor[4], aS4[4], bXor[4], bS4[4];
#pragma unroll
    for (int mi = 0; mi < 4; mi++) {
        int r = wm + mi * 16 + aRowOff;
        aBase[mi] = (uint32_t)(r >> 1) << 7;
        aXor[mi] = (r >> 1) & 7;
        aS4[mi] = (r & 1) << 2;
    }
#pragma unroll
    for (int ni = 0; ni < 4; ni++) {
        int r = wn + ni * 8 + lr;
        bBase[ni] = (uint32_t)(r >> 1) << 7;
        bXor[ni] = (r >> 1) & 7;
        bS4[ni] = (r & 1) << 2;
    }

    float acc[4][4][4];
#pragma unroll
    for (int mi = 0; mi < 4; mi++)
#pragma unroll
        for (int ni = 0; ni < 4; ni++)
#pragma unroll
            for (int q = 0; q < 4; q++) acc[mi][ni][q] = 0.f;

    const unsigned char* Asrc = Ap + (size_t)blockIdx.x * HTILE_BYTES;
    const unsigned char* Bsrc0 = Wslot + (size_t)nh * 8192;

    {
#pragma unroll
        for (int j = 0; j < 2; j++) {
            int idx = tid + j * 256;
            cp16(sb + idx * 16, Asrc + idx * 16);
            cp16(sb + 8192 + idx * 16, Bsrc0 + idx * 16);
        }
        cp_commit();
    }

    for (int c = 0; c < 8; c++) {
        int p = c & 1;
        if (c < 7) {
            uint32_t sB = sb + (p ^ 1) * STAGE_BYTES;
            const unsigned char* ga = Asrc + (size_t)(c + 1) * 8192;
            const unsigned char* gb = Bsrc0 + (size_t)(c + 1) * 16384;
#pragma unroll
            for (int j = 0; j < 2; j++) {
                int idx = tid + j * 256;
                cp16(sB + idx * 16, ga + idx * 16);
                cp16(sB + 8192 + idx * 16, gb + idx * 16);
            }
            cp_commit();
            asm volatile("cp.async.wait_group 1;" ::: "memory");
        } else {
            asm volatile("cp.async.wait_group 0;" ::: "memory");
        }
        __syncthreads();

        uint32_t bufb = sb + p * STAGE_BYTES;
        uint32_t sA = bufb;
        uint32_t sB = bufb + 8192;

#pragma unroll
        for (int ks = 0; ks < 2; ks++) {
            int ka = ks * 2 + aCc;
            int kb = ks * 2 + bCc;
            uint32_t ah[4][4];
#pragma unroll
            for (int mi = 0; mi < 4; mi++)
                ldx4(ah[mi], sA + aBase[mi] + ((uint32_t)((ka + aS4[mi]) ^ aXor[mi]) << 4));
            uint32_t b[4][2];
#pragma unroll
            for (int ni = 0; ni < 4; ni++)
                ldx2(b[ni], sB + bBase[ni] + ((uint32_t)((kb + bS4[ni]) ^ bXor[ni]) << 4));
#pragma unroll
            for (int mi = 0; mi < 4; mi++)
#pragma unroll
                for (int ni = 0; ni < 4; ni++) mma16816h(acc[mi][ni], ah[mi], b[ni]);
        }
        __syncthreads();
    }

    // ---- epilogue: write compact fp16 plane ----
    float sc[4][2], sh[4][2];
#pragma unroll
    for (int ni = 0; ni < 4; ni++) {
#pragma unroll
        for (int j = 0; j < 2; j++) {
            int col = nh * 128 + wn + ni * 8 + (lane & 3) * 2 + j;
            float bv = bias[col];
            if (DO_BN) {
                float s = gamma[col] * rsqrtf(var[col] + BN_EPS);
                sc[ni][j] = s;
                sh[ni][j] = beta[col] - mean[col] * s + bv * s;
            } else {
                sc[ni][j] = 1.f;
                sh[ni][j] = bv;
            }
        }
    }
#pragma unroll
    for (int mi = 0; mi < 4; mi++) {
        int rl0 = wm + mi * 16 + (lane >> 2);
        int rl1 = rl0 + 8;
#pragma unroll
        for (int ni = 0; ni < 4; ni++) {
            int c0g = nh * 128 + wn + ni * 8 + (lane & 3) * 2;
            float v0 = fmaxf(acc[mi][ni][0] * sc[ni][0] + sh[ni][0], 0.f);
            float v1 = fmaxf(acc[mi][ni][1] * sc[ni][1] + sh[ni][1], 0.f);
            float v2 = fmaxf(acc[mi][ni][2] * sc[ni][0] + sh[ni][0], 0.f);
            float v3 = fmaxf(acc[mi][ni][3] * sc[ni][1] + sh[ni][1], 0.f);
            int ch = c0g >> 5, kl = c0g & 31;
            uint32_t bib = (uint32_t)(kl & 7) * 2;
            unsigned char* tb = Oplanes + (size_t)blockIdx.x * HTILE_BYTES + (size_t)ch * 8192;
            if (rowBase + rl0 < M)
                *(uint32_t*)(tb + tswz(rl0, kl >> 3) + bib) = packhf2(v0, v1);
            if (rowBase + rl1 < M)
                *(uint32_t*)(tb + tswz(rl1, kl >> 3) + bib) = packhf2(v2, v3);
        }
    }
}

// ---------------- pooling (reads compact fp16 planes) ----------------
__global__ void pool_kernel(const unsigned char* __restrict__ hp1,
                            const unsigned char* __restrict__ hp2,
                            const void* __restrict__ batch) {
    int wid = blockIdx.x * 8 + (threadIdx.x >> 5);
    int base = wid * 16;
    if (base >= N_NODES) return;
    int lane = threadIdx.x & 31;
    int end = base + 16; if (end > N_NODES) end = N_NODES;

    float4 a0 = {0,0,0,0}, a1 = {0,0,0,0}, b0 = {0,0,0,0}, b1 = {0,0,0,0};
    int cur = load_idx(batch, base);
    for (int n = base; n < end; n++) {
        int g = load_idx(batch, n);
        if (g != cur) {
            float* p = g_pool + (size_t)cur * 512 + lane * 4;
            atomicAdd(p + 0, a0.x); atomicAdd(p + 1, a0.y); atomicAdd(p + 2, a0.z); atomicAdd(p + 3, a0.w);
            atomicAdd(p + 128, a1.x); atomicAdd(p + 129, a1.y); atomicAdd(p + 130, a1.z); atomicAdd(p + 131, a1.w);
            atomicAdd(p + 256, b0.x); atomicAdd(p + 257, b0.y); atomicAdd(p + 258, b0.z); atomicAdd(p + 259, b0.w);
            atomicAdd(p + 384, b1.x); atomicAdd(p + 385, b1.y); atomicAdd(p + 386, b1.z); atomicAdd(p + 387, b1.w);
            a0 = a1 = b0 = b1 = make_float4(0,0,0,0);
            cur = g;
        }
        float4 v0, v1;
        plane_row_load(hp1, n, lane, v0, v1);
        a0.x += v0.x; a0.y += v0.y; a0.z += v0.z; a0.w += v0.w;
        a1.x += v1.x; a1.y += v1.y; a1.z += v1.z; a1.w += v1.w;
        plane_row_load(hp2, n, lane, v0, v1);
        b0.x += v0.x; b0.y += v0.y; b0.z += v0.z; b0.w += v0.w;
        b1.x += v1.x; b1.y += v1.y; b1.z += v1.z; b1.w += v1.w;
    }
    float* p = g_pool + (size_t)cur * 512 + lane * 4;
    atomicAdd(p + 0, a0.x); atomicAdd(p + 1, a0.y); atomicAdd(p + 2, a0.z); atomicAdd(p + 3, a0.w);
    atomicAdd(p + 128, a1.x); atomicAdd(p + 129, a1.y); atomicAdd(p + 130, a1.z); atomicAdd(p + 131, a1.w);
    atomicAdd(p + 256, b0.x); atomicAdd(p + 257, b0.y); atomicAdd(p + 258, b0.z); atomicAdd(p + 259, b0.w);
    atomicAdd(p + 384, b1.x); atomicAdd(p + 385, b1.y); atomicAdd(p + 386, b1.z); atomicAdd(p + 387, b1.w);
}

// ---------------- head ----------------
__global__ __launch_bounds__(256) void head_kernel(
    const float* __restrict__ W1, const float* __restrict__ b1,
    const float* __restrict__ W2, const float* __restrict__ b2,
    float* __restrict__ out)
{
    __shared__ float Ps[8][512];
    __shared__ float Hs[8][768];
    __shared__ float Os[8][10];
    int tid = threadIdx.x;
    int rowBase = blockIdx.x * 8;
    int nrows = N_GRAPHS - rowBase; if (nrows > 8) nrows = 8;

    for (int i = tid; i < 8 * 512; i += 256) {
        int r = i >> 9, c = i & 511;
        Ps[r][c] = (r < nrows) ? g_pool[(size_t)(rowBase + r) * 512 + c] : 0.f;
    }
    __syncthreads();

    for (int n = tid; n < 768; n += 256) {
        float acc[8];
#pragma unroll
        for (int r = 0; r < 8; r++) acc[r] = 0.f;
        for (int k = 0; k < 512; k++) {
            float w = W1[(size_t)k * 768 + n];
#pragma unroll
            for (int r = 0; r < 8; r++) acc[r] = fmaf(Ps[r][k], w, acc[r]);
        }
        float bb = b1[n];
#pragma unroll
        for (int r = 0; r < 8; r++) Hs[r][n] = fmaxf(acc[r] + bb, 0.f);
    }
    __syncthreads();

    if (tid < 80) {
        int r = tid / 10, c = tid % 10;
        float acc = b2[c];
        for (int k = 0; k < 768; k++) acc = fmaf(Hs[r][k], W2[(size_t)k * 10 + c], acc);
        Os[r][c] = acc;
    }
    __syncthreads();

    if (tid < nrows) {
        int r = tid;
        float mx = -1e30f;
        for (int c = 0; c < 10; c++) mx = fmaxf(mx, Os[r][c]);
        float s = 0.f;
        for (int c = 0; c < 10; c++) s += expf(Os[r][c] - mx);
        float lse = mx + logf(s);
        for (int c = 0; c < 10; c++) out[(size_t)(rowBase + r) * 10 + c] = Os[r][c] - lse;
    }
}

// ---------------- launch ----------------
extern "C" void kernel_launch(void* const* d_in, const int* in_sizes, int n_in,
                              void* d_out, int out_size) {
    const float* x     = (const float*)d_in[0];
    const void*  ei    = d_in[1];
    const void*  batch = d_in[2];
    const float* W1a = (const float*)d_in[3];
    const float* b1a = (const float*)d_in[4];
    const float* g1a = (const float*)d_in[5];
    const float* be1a= (const float*)d_in[6];
    const float* m1a = (const float*)d_in[7];
    const float* v1a = (const float*)d_in[8];
    const float* W2a = (const float*)d_in[9];
    const float* b2a = (const float*)d_in[10];
    const float* W1b = (const float*)d_in[11];
    const float* b1b = (const float*)d_in[12];
    const float* g1b = (const float*)d_in[13];
    const float* be1b= (const float*)d_in[14];
    const float* m1b = (const float*)d_in[15];
    const float* v1b = (const float*)d_in[16];
    const float* W2b = (const float*)d_in[17];
    const float* b2b = (const float*)d_in[18];
    const float* lin1W = (const float*)d_in[19];
    const float* lin1b = (const float*)d_in[20];
    const float* lin2W = (const float*)d_in[21];
    const float* lin2b = (const float*)d_in[22];
    float* out = (float*)d_out;

    unsigned char *px, *pl0, *pl1, *hp1, *hp2, *wt;
    cudaGetSymbolAddress((void**)&px,  g_px);
    cudaGetSymbolAddress((void**)&pl0, g_pl0);
    cudaGetSymbolAddress((void**)&pl1, g_pl1);
    cudaGetSymbolAddress((void**)&hp1, g_hp1);
    cudaGetSymbolAddress((void**)&hp2, g_hp2);
    cudaGetSymbolAddress((void**)&wt,  g_wt);

    cudaFuncSetAttribute(gemm_mma_kernel<true>,  cudaFuncAttributeMaxDynamicSharedMemorySize, GSM_BYTES);
    cudaFuncSetAttribute(gemm_mma_kernel<false>, cudaFuncAttributeMaxDynamicSharedMemorySize, GSM_BYTES);

    dim3 gemmGrid(N_TILES, 2);
    const int aggGrid  = (N_NODES + 7) / 8;
    const int scanGrid = (N_NODES + 1023) / 1024; // 49

    // detect + zero counts
    detect_zero_kernel<<<(N_NODES + 255) / 256, 256>>>((const long long*)ei);

    // fused wconv + hist + pool-zero + xconv
    prep_kernel<<<WCONV_BLOCKS + HIST_BLOCKS + XCONV_BLOCKS, 256>>>(ei, x, W1a, W2a, W1b, W2b);

    // CSR build
    scan1_kernel<<<scanGrid, 1024>>>();
    scan3_kernel<<<scanGrid, 1024>>>(scanGrid);
    fill_kernel<<<(N_EDGES + 255) / 256, 256>>>(ei);

    // layer 1
    agg_kernel<<<aggGrid, 256>>>(px, pl0);
    gemm_mma_kernel<true ><<<gemmGrid, 256, GSM_BYTES>>>(
        pl0, wt + 0 * 131072, b1a, g1a, be1a, m1a, v1a, pl1, N_NODES);
    gemm_mma_kernel<false><<<gemmGrid, 256, GSM_BYTES>>>(
        pl1, wt + 1 * 131072, b2a, nullptr, nullptr, nullptr, nullptr, hp1, N_NODES);

    // layer 2
    agg_kernel<<<aggGrid, 256>>>(hp1, pl0);
    gemm_mma_kernel<true ><<<gemmGrid, 256, GSM_BYTES>>>(
        pl0, wt + 2 * 131072, b1b, g1b, be1b, m1b, v1b, pl1, N_NODES);
    gemm_mma_kernel<false><<<gemmGrid, 256, GSM_BYTES>>>(
        pl1, wt + 3 * 131072, b2b, nullptr, nullptr, nullptr, nullptr, hp2, N_NODES);

    // pooling (g_pool zeroed inside prep_kernel)
    pool_kernel<<<((N_NODES + 15) / 16 + 7) / 8, 256>>>(hp1, hp2, batch);

    // head
    head_kernel<<<(N_GRAPHS + 7) / 8, 256>>>(lin1W, lin1b, lin2W, lin2b, out);
}

// round 17
// speedup vs baseline: 1.2220x; 1.0158x over previous
#include <cuda_runtime.h>
#include <cuda_fp16.h>
#include <cstdint>

#define N_NODES 50000
#define N_EDGES 800000
#define DIM 256
#define N_GRAPHS 500
#define N_OUT 10
#define BN_EPS 1e-5f

#define N_TILES 391              // ceil(50000/128)
#define HTILE_BYTES 65536        // compact fp16 planes: 8 chunks * 8KB

// ---------------- scratch ----------------
__device__ unsigned char g_px [(size_t)N_TILES * HTILE_BYTES];
__device__ unsigned char g_pl0[(size_t)N_TILES * HTILE_BYTES];
__device__ unsigned char g_pl1[(size_t)N_TILES * HTILE_BYTES];
__device__ unsigned char g_hp1[(size_t)N_TILES * HTILE_BYTES];
__device__ unsigned char g_hp2[(size_t)N_TILES * HTILE_BYTES];
__device__ float g_pool[(size_t)N_GRAPHS * 2 * DIM];
__device__ int   g_idx_is64;
__device__ int   g_counts[N_NODES];
__device__ int   g_rowptr[N_NODES + 1];
__device__ int   g_cursor[N_NODES];
__device__ int   g_esrc[N_EDGES];
__device__ int   g_partials[64];
// weights (single fp16): [slot][chunk=8][nhalf=2][8192B] = 128KB/slot
__device__ unsigned char g_wt[4 * 131072];

// ---------------- helpers ----------------
__device__ __forceinline__ uint32_t smem_u32(const void* p) {
    uint32_t a;
    asm("{ .reg .u64 t; cvta.to.shared.u64 t, %1; cvt.u32.u64 %0, t; }" : "=r"(a) : "l"(p));
    return a;
}
__device__ __forceinline__ void cp16(uint32_t s, const void* g) {
    asm volatile("cp.async.cg.shared.global [%0], [%1], 16;"
                 :: "r"(s), "l"(__cvta_generic_to_global(g)) : "memory");
}
__device__ __forceinline__ void cp_commit() { asm volatile("cp.async.commit_group;" ::: "memory"); }
__device__ __forceinline__ void ldx4(uint32_t* r, uint32_t addr) {
    asm volatile("ldmatrix.sync.aligned.m8n8.x4.shared.b16 {%0,%1,%2,%3}, [%4];"
                 : "=r"(r[0]), "=r"(r[1]), "=r"(r[2]), "=r"(r[3]) : "r"(addr));
}
__device__ __forceinline__ void ldx2(uint32_t* r, uint32_t addr) {
    asm volatile("ldmatrix.sync.aligned.m8n8.x2.shared.b16 {%0,%1}, [%2];"
                 : "=r"(r[0]), "=r"(r[1]) : "r"(addr));
}
__device__ __forceinline__ void mma16816h(float* d, const uint32_t* a, const uint32_t* b) {
    asm volatile("mma.sync.aligned.m16n8k16.row.col.f32.f16.f16.f32 "
                 "{%0,%1,%2,%3}, {%4,%5,%6,%7}, {%8,%9}, {%0,%1,%2,%3};"
                 : "+f"(d[0]), "+f"(d[1]), "+f"(d[2]), "+f"(d[3])
                 : "r"(a[0]), "r"(a[1]), "r"(a[2]), "r"(a[3]), "r"(b[0]), "r"(b[1]));
}
__device__ __forceinline__ uint32_t tswz(int r, int ccol) {
    int rr = r >> 1;
    return ((uint32_t)rr << 7) + ((uint32_t)((ccol + ((r & 1) << 2)) ^ (rr & 7)) << 4);
}
__device__ __forceinline__ uint32_t packhf2(float a, float b) {
    __half2 h = __floats2half2_rn(a, b);
    return *(uint32_t*)&h;
}
__device__ __forceinline__ void plane_row_load(const unsigned char* P, int s, int lane,
                                               float4& v0, float4& v1) {
    int tile = s >> 7, r = s & 127;
    int ccol = (lane >> 1) & 3, c0 = lane >> 3;
    uint32_t off = tswz(r, ccol) + (uint32_t)(lane & 1) * 8;
    const unsigned char* base = P + (size_t)tile * HTILE_BYTES;
    uint2 u0 = *(const uint2*)(base + (size_t)c0 * 8192 + off);
    uint2 u1 = *(const uint2*)(base + (size_t)(c0 + 4) * 8192 + off);
    float2 f;
    f = __half22float2(*(__half2*)&u0.x); v0.x = f.x; v0.y = f.y;
    f = __half22float2(*(__half2*)&u0.y); v0.z = f.x; v0.w = f.y;
    f = __half22float2(*(__half2*)&u1.x); v1.x = f.x; v1.y = f.y;
    f = __half22float2(*(__half2*)&u1.y); v1.z = f.x; v1.w = f.y;
}
__device__ __forceinline__ void plane_row_store(unsigned char* P, int node, int lane,
                                                const float4& a0, const float4& a1) {
    int tile = node >> 7, r = node & 127;
    int ccol = (lane >> 1) & 3, c0 = lane >> 3;
    uint32_t off = tswz(r, ccol) + (uint32_t)(lane & 1) * 8;
    unsigned char* base = P + (size_t)tile * HTILE_BYTES;
    *(uint2*)(base + (size_t)c0 * 8192 + off) =
        make_uint2(packhf2(a0.x, a0.y), packhf2(a0.z, a0.w));
    *(uint2*)(base + (size_t)(c0 + 4) * 8192 + off) =
        make_uint2(packhf2(a1.x, a1.y), packhf2(a1.z, a1.w));
}

// ---------------- dtype detection ----------------
__device__ __forceinline__ int load_idx(const void* p, int i) {
    if (g_idx_is64) return (int)((const long long*)p)[i];
    return ((const int*)p)[i];
}

// ---------------- detect + zero counts (fused) ----------------
__global__ void detect_zero_kernel(const long long* __restrict__ ei) {
    int i = blockIdx.x * blockDim.x + threadIdx.x;
    if (i < N_NODES) g_counts[i] = 0;
    if (i == 0) {
        int ok = 1;
        for (int j = 0; j < 64; j++) {
            long long v = ei[j];
            if (v < 0 || v >= N_NODES) ok = 0;
        }
        g_idx_is64 = ok;
    }
}

// ---------------- fused weight-conv + x-conv + histogram + pool-zero ----------------
#define WCONV_BLOCKS 1024
#define HIST_BLOCKS  3125
#define XCONV_BLOCKS 6250
__global__ void prep_kernel(const void* __restrict__ ei, const float* __restrict__ x,
                            const float* __restrict__ Wa, const float* __restrict__ Wb,
                            const float* __restrict__ Wc, const float* __restrict__ Wd) {
    int b = blockIdx.x;
    if (b < WCONV_BLOCKS) {
        int slot = b >> 8;
        const float* W = (slot == 0) ? Wa : (slot == 1) ? Wb : (slot == 2) ? Wc : Wd;
        int id = (b & 255) * 256 + threadIdx.x;
        int k = id >> 8, n = id & 255;
        float v = W[(size_t)k * 256 + n];
        int c = k >> 5, kl = k & 31, h = n >> 7, r = n & 127;
        uint32_t off = tswz(r, kl >> 3) + (uint32_t)(kl & 7) * 2;
        size_t base = (size_t)slot * 131072 + (size_t)c * 16384 + (size_t)h * 8192;
        *(__half*)(g_wt + base + off) = __float2half_rn(v);
    } else if (b < WCONV_BLOCKS + HIST_BLOCKS) {
        int e = (b - WCONV_BLOCKS) * 256 + threadIdx.x;
        if (e < N_GRAPHS * 2 * DIM) g_pool[e] = 0.f;
        if (e >= N_EDGES) return;
        atomicAdd(&g_counts[load_idx(ei, N_EDGES + e)], 1);
    } else {
        int node = (b - WCONV_BLOCKS - HIST_BLOCKS) * 8 + (threadIdx.x >> 5);
        if (node >= N_NODES) return;
        int lane = threadIdx.x & 31;
        const float4* xv = (const float4*)x;
        float4 a0 = xv[(size_t)node * 64 + lane];
        float4 a1 = xv[(size_t)node * 64 + 32 + lane];
        plane_row_store(g_px, node, lane, a0, a1);
    }
}

__global__ void scan1_kernel() {
    __shared__ int wsum[32];
    int tid = threadIdx.x;
    int i = blockIdx.x * 1024 + tid;
    int v = (i < N_NODES) ? g_counts[i] : 0;
    int s = v;
    int lane = tid & 31;
#pragma unroll
    for (int o = 1; o < 32; o <<= 1) {
        int t = __shfl_up_sync(0xffffffffu, s, o);
        if (lane >= o) s += t;
    }
    if (lane == 31) wsum[tid >> 5] = s;
    __syncthreads();
    if (tid < 32) {
        int ws = wsum[tid];
#pragma unroll
        for (int o = 1; o < 32; o <<= 1) {
            int t = __shfl_up_sync(0xffffffffu, ws, o);
            if (tid >= o) ws += t;
        }
        wsum[tid] = ws;
    }
    __syncthreads();
    int off = (tid >= 32) ? wsum[(tid >> 5) - 1] : 0;
    int incl = s + off;
    if (i < N_NODES) g_rowptr[i] = incl - v;
    if (tid == 1023) g_partials[blockIdx.x] = incl;
}
__global__ void scan3_kernel(int nblk) {
    __shared__ int soff;
    int tid = threadIdx.x;
    if (tid < 32) {
        int acc = 0;
        int j0 = tid, j1 = tid + 32;
        if (j0 < nblk && j0 < blockIdx.x) acc += g_partials[j0];
        if (j1 < nblk && j1 < blockIdx.x) acc += g_partials[j1];
#pragma unroll
        for (int o = 16; o > 0; o >>= 1) acc += __shfl_down_sync(0xffffffffu, acc, o);
        if (tid == 0) soff = acc;
    }
    __syncthreads();
    int i = blockIdx.x * 1024 + tid;
    if (i < N_NODES) {
        int r = g_rowptr[i] + soff;
        g_rowptr[i] = r;
        g_cursor[i] = r;
    }
    if (i == 0) g_rowptr[N_NODES] = N_EDGES;
}
__global__ void fill_kernel(const void* __restrict__ ei) {
    int e = blockIdx.x * blockDim.x + threadIdx.x;
    if (e >= N_EDGES) return;
    int s = load_idx(ei, e);
    int d = load_idx(ei, N_EDGES + e);
    g_esrc[atomicAdd(&g_cursor[d], 1)] = s;
}

// ---------------- gather aggregation (plane -> plane), 2-way unroll ----------------
__global__ __launch_bounds__(256) void agg_kernel(const unsigned char* __restrict__ Ip,
                                                  unsigned char* __restrict__ Op) {
    int node = blockIdx.x * 8 + (threadIdx.x >> 5);
    if (node >= N_NODES) return;
    int lane = threadIdx.x & 31;
    float4 acc0, acc1;
    plane_row_load(Ip, node, lane, acc0, acc1);
    int start = g_rowptr[node];
    int end   = g_rowptr[node + 1];
    int k = start;
    for (; k + 1 < end; k += 2) {
        int sa = g_esrc[k];
        int sb = g_esrc[k + 1];
        float4 a0, a1, b0, b1;
        plane_row_load(Ip, sa, lane, a0, a1);
        plane_row_load(Ip, sb, lane, b0, b1);
        acc0.x += a0.x + b0.x; acc0.y += a0.y + b0.y;
        acc0.z += a0.z + b0.z; acc0.w += a0.w + b0.w;
        acc1.x += a1.x + b1.x; acc1.y += a1.y + b1.y;
        acc1.z += a1.z + b1.z; acc1.w += a1.w + b1.w;
    }
    if (k < end) {
        int sa = g_esrc[k];
        float4 a0, a1;
        plane_row_load(Ip, sa, lane, a0, a1);
        acc0.x += a0.x; acc0.y += a0.y; acc0.z += a0.z; acc0.w += a0.w;
        acc1.x += a1.x; acc1.y += a1.y; acc1.z += a1.z; acc1.w += a1.w;
    }
    plane_row_store(Op, node, lane, acc0, acc1);
}

// ---------------- single-pass fp16 GEMM, K-chunk 64 (4 chunks, half the syncs) ----------------
// grid (N_TILES, 2), 256 threads, 2 CTAs/SM. Stage = A(16KB) + B(16KB) = 32KB, x2 = 64KB.
#define STAGE_BYTES 32768
#define GSM_BYTES (2 * STAGE_BYTES + 1024)

template <bool DO_BN>
__global__ __launch_bounds__(256, 2) void gemm_mma_kernel(
    const unsigned char* __restrict__ Ap, const unsigned char* __restrict__ Wslot,
    const float* __restrict__ bias,
    const float* __restrict__ gamma, const float* __restrict__ beta,
    const float* __restrict__ mean,  const float* __restrict__ var,
    unsigned char* __restrict__ Oplanes, int M)
{
    extern __shared__ char dsm[];
    uint32_t sb0 = smem_u32(dsm);
    uint32_t sb = (sb0 + 1023u) & ~1023u;

    const int tid = threadIdx.x, wid = tid >> 5, lane = tid & 31;
    const int rowBase = blockIdx.x * 128;
    const int nh = blockIdx.y;
    const int wm = (wid >> 2) * 64;
    const int wn = (wid & 3) * 32;

    const int lr = lane & 7;
    const int ag = lane >> 3;
    const int aRowOff = (ag & 1) * 8 + lr;
    const int aCc = ag >> 1;
    const int bCc = (lane >> 3) & 1;

    uint32_t aBase[4], bBase[4];
    int aXor[4], aS4[4], bXor[4], bS4[4];
#pragma unroll
    for (int mi = 0; mi < 4; mi++) {
        int r = wm + mi * 16 + aRowOff;
        aBase[mi] = (uint32_t)(r >> 1) << 7;
        aXor[mi] = (r >> 1) & 7;
        aS4[mi] = (r & 1) << 2;
    }
#pragma unroll
    for (int ni = 0; ni < 4; ni++) {
        int r = wn + ni * 8 + lr;
        bBase[ni] = (uint32_t)(r >> 1) << 7;
        bXor[ni] = (r >> 1) & 7;
        bS4[ni] = (r & 1) << 2;
    }

    float acc[4][4][4];
#pragma unroll
    for (int mi = 0; mi < 4; mi++)
#pragma unroll
        for (int ni = 0; ni < 4; ni++)
#pragma unroll
            for (int q = 0; q < 4; q++) acc[mi][ni][q] = 0.f;

    const unsigned char* Asrc = Ap + (size_t)blockIdx.x * HTILE_BYTES;
    const unsigned char* Bsrc0 = Wslot + (size_t)nh * 8192;

    // stage layout: [A 16KB (2x8KB sub-chunks)] [B 16KB (2x8KB sub-chunks)]
    // prefetch chunk64 0: A bytes [0,16384), B sub-chunks 0,1 at 0 and 16384
    {
#pragma unroll
        for (int j = 0; j < 4; j++) {
            int idx = tid + j * 256;          // 1024 x 16B = 16KB (A)
            cp16(sb + idx * 16, Asrc + idx * 16);
        }
#pragma unroll
        for (int j = 0; j < 2; j++) {
            int idx = tid + j * 256;          // 512 x 16B per B sub-chunk
            cp16(sb + 16384 + idx * 16, Bsrc0 + idx * 16);
            cp16(sb + 24576 + idx * 16, Bsrc0 + 16384 + idx * 16);
        }
        cp_commit();
    }

    for (int c = 0; c < 4; c++) {
        int p = c & 1;
        if (c < 3) {
            uint32_t sB = sb + (p ^ 1) * STAGE_BYTES;
            const unsigned char* ga = Asrc + (size_t)(c + 1) * 16384;
            const unsigned char* gb = Bsrc0 + (size_t)(c + 1) * 32768;
#pragma unroll
            for (int j = 0; j < 4; j++) {
                int idx = tid + j * 256;
                cp16(sB + idx * 16, ga + idx * 16);
            }
#pragma unroll
            for (int j = 0; j < 2; j++) {
                int idx = tid + j * 256;
                cp16(sB + 16384 + idx * 16, gb + idx * 16);
                cp16(sB + 24576 + idx * 16, gb + 16384 + idx * 16);
            }
            cp_commit();
            asm volatile("cp.async.wait_group 1;" ::: "memory");
        } else {
            asm volatile("cp.async.wait_group 0;" ::: "memory");
        }
        __syncthreads();

        uint32_t bufb = sb + p * STAGE_BYTES;

#pragma unroll
        for (int half = 0; half < 2; half++) {
            uint32_t sA = bufb + (uint32_t)half * 8192;
            uint32_t sB = bufb + 16384 + (uint32_t)half * 8192;
#pragma unroll
            for (int ks = 0; ks < 2; ks++) {
                int ka = ks * 2 + aCc;
                int kb = ks * 2 + bCc;
                uint32_t ah[4][4];
#pragma unroll
                for (int mi = 0; mi < 4; mi++)
                    ldx4(ah[mi], sA + aBase[mi] + ((uint32_t)((ka + aS4[mi]) ^ aXor[mi]) << 4));
                uint32_t b[4][2];
#pragma unroll
                for (int ni = 0; ni < 4; ni++)
                    ldx2(b[ni], sB + bBase[ni] + ((uint32_t)((kb + bS4[ni]) ^ bXor[ni]) << 4));
#pragma unroll
                for (int mi = 0; mi < 4; mi++)
#pragma unroll
                    for (int ni = 0; ni < 4; ni++) mma16816h(acc[mi][ni], ah[mi], b[ni]);
            }
        }
        __syncthreads();
    }

    // ---- epilogue: write compact fp16 plane ----
    float sc[4][2], sh[4][2];
#pragma unroll
    for (int ni = 0; ni < 4; ni++) {
#pragma unroll
        for (int j = 0; j < 2; j++) {
            int col = nh * 128 + wn + ni * 8 + (lane & 3) * 2 + j;
            float bv = bias[col];
            if (DO_BN) {
                float s = gamma[col] * rsqrtf(var[col] + BN_EPS);
                sc[ni][j] = s;
                sh[ni][j] = beta[col] - mean[col] * s + bv * s;
            } else {
                sc[ni][j] = 1.f;
                sh[ni][j] = bv;
            }
        }
    }
#pragma unroll
    for (int mi = 0; mi < 4; mi++) {
        int rl0 = wm + mi * 16 + (lane >> 2);
        int rl1 = rl0 + 8;
#pragma unroll
        for (int ni = 0; ni < 4; ni++) {
            int c0g = nh * 128 + wn + ni * 8 + (lane & 3) * 2;
            float v0 = fmaxf(acc[mi][ni][0] * sc[ni][0] + sh[ni][0], 0.f);
            float v1 = fmaxf(acc[mi][ni][1] * sc[ni][1] + sh[ni][1], 0.f);
            float v2 = fmaxf(acc[mi][ni][2] * sc[ni][0] + sh[ni][0], 0.f);
            float v3 = fmaxf(acc[mi][ni][3] * sc[ni][1] + sh[ni][1], 0.f);
            int ch = c0g >> 5, kl = c0g & 31;
            uint32_t bib = (uint32_t)(kl & 7) * 2;
            unsigned char* tb = Oplanes + (size_t)blockIdx.x * HTILE_BYTES + (size_t)ch * 8192;
            if (rowBase + rl0 < M)
                *(uint32_t*)(tb + tswz(rl0, kl >> 3) + bib) = packhf2(v0, v1);
            if (rowBase + rl1 < M)
                *(uint32_t*)(tb + tswz(rl1, kl >> 3) + bib) = packhf2(v2, v3);
        }
    }
}

// ---------------- pooling (reads compact fp16 planes) ----------------
__global__ void pool_kernel(const unsigned char* __restrict__ hp1,
                            const unsigned char* __restrict__ hp2,
                            const void* __restrict__ batch) {
    int wid = blockIdx.x * 8 + (threadIdx.x >> 5);
    int base = wid * 16;
    if (base >= N_NODES) return;
    int lane = threadIdx.x & 31;
    int end = base + 16; if (end > N_NODES) end = N_NODES;

    float4 a0 = {0,0,0,0}, a1 = {0,0,0,0}, b0 = {0,0,0,0}, b1 = {0,0,0,0};
    int cur = load_idx(batch, base);
    for (int n = base; n < end; n++) {
        int g = load_idx(batch, n);
        if (g != cur) {
            float* p = g_pool + (size_t)cur * 512 + lane * 4;
            atomicAdd(p + 0, a0.x); atomicAdd(p + 1, a0.y); atomicAdd(p + 2, a0.z); atomicAdd(p + 3, a0.w);
            atomicAdd(p + 128, a1.x); atomicAdd(p + 129, a1.y); atomicAdd(p + 130, a1.z); atomicAdd(p + 131, a1.w);
            atomicAdd(p + 256, b0.x); atomicAdd(p + 257, b0.y); atomicAdd(p + 258, b0.z); atomicAdd(p + 259, b0.w);
            atomicAdd(p + 384, b1.x); atomicAdd(p + 385, b1.y); atomicAdd(p + 386, b1.z); atomicAdd(p + 387, b1.w);
            a0 = a1 = b0 = b1 = make_float4(0,0,0,0);
            cur = g;
        }
        float4 v0, v1;
        plane_row_load(hp1, n, lane, v0, v1);
        a0.x += v0.x; a0.y += v0.y; a0.z += v0.z; a0.w += v0.w;
        a1.x += v1.x; a1.y += v1.y; a1.z += v1.z; a1.w += v1.w;
        plane_row_load(hp2, n, lane, v0, v1);
        b0.x += v0.x; b0.y += v0.y; b0.z += v0.z; b0.w += v0.w;
        b1.x += v1.x; b1.y += v1.y; b1.z += v1.z; b1.w += v1.w;
    }
    float* p = g_pool + (size_t)cur * 512 + lane * 4;
    atomicAdd(p + 0, a0.x); atomicAdd(p + 1, a0.y); atomicAdd(p + 2, a0.z); atomicAdd(p + 3, a0.w);
    atomicAdd(p + 128, a1.x); atomicAdd(p + 129, a1.y); atomicAdd(p + 130, a1.z); atomicAdd(p + 131, a1.w);
    atomicAdd(p + 256, b0.x); atomicAdd(p + 257, b0.y); atomicAdd(p + 258, b0.z); atomicAdd(p + 259, b0.w);
    atomicAdd(p + 384, b1.x); atomicAdd(p + 385, b1.y); atomicAdd(p + 386, b1.z); atomicAdd(p + 387, b1.w);
}

// ---------------- head ----------------
__global__ __launch_bounds__(256) void head_kernel(
    const float* __restrict__ W1, const float* __restrict__ b1,
    const float* __restrict__ W2, const float* __restrict__ b2,
    float* __restrict__ out)
{
    __shared__ float Ps[8][512];
    __shared__ float Hs[8][768];
    __shared__ float Os[8][10];
    int tid = threadIdx.x;
    int rowBase = blockIdx.x * 8;
    int nrows = N_GRAPHS - rowBase; if (nrows > 8) nrows = 8;

    for (int i = tid; i < 8 * 512; i += 256) {
        int r = i >> 9, c = i & 511;
        Ps[r][c] = (r < nrows) ? g_pool[(size_t)(rowBase + r) * 512 + c] : 0.f;
    }
    __syncthreads();

    for (int n = tid; n < 768; n += 256) {
        float acc[8];
#pragma unroll
        for (int r = 0; r < 8; r++) acc[r] = 0.f;
        for (int k = 0; k < 512; k++) {
            float w = W1[(size_t)k * 768 + n];
#pragma unroll
            for (int r = 0; r < 8; r++) acc[r] = fmaf(Ps[r][k], w, acc[r]);
        }
        float bb = b1[n];
#pragma unroll
        for (int r = 0; r < 8; r++) Hs[r][n] = fmaxf(acc[r] + bb, 0.f);
    }
    __syncthreads();

    if (tid < 80) {
        int r = tid / 10, c = tid % 10;
        float acc = b2[c];
        for (int k = 0; k < 768; k++) acc = fmaf(Hs[r][k], W2[(size_t)k * 10 + c], acc);
        Os[r][c] = acc;
    }
    __syncthreads();

    if (tid < nrows) {
        int r = tid;
        float mx = -1e30f;
        for (int c = 0; c < 10; c++) mx = fmaxf(mx, Os[r][c]);
        float s = 0.f;
        for (int c = 0; c < 10; c++) s += expf(Os[r][c] - mx);
        float lse = mx + logf(s);
        for (int c = 0; c < 10; c++) out[(size_t)(rowBase + r) * 10 + c] = Os[r][c] - lse;
    }
}

// ---------------- launch ----------------
extern "C" void kernel_launch(void* const* d_in, const int* in_sizes, int n_in,
                              void* d_out, int out_size) {
    const float* x     = (const float*)d_in[0];
    const void*  ei    = d_in[1];
    const void*  batch = d_in[2];
    const float* W1a = (const float*)d_in[3];
    const float* b1a = (const float*)d_in[4];
    const float* g1a = (const float*)d_in[5];
    const float* be1a= (const float*)d_in[6];
    const float* m1a = (const float*)d_in[7];
    const float* v1a = (const float*)d_in[8];
    const float* W2a = (const float*)d_in[9];
    const float* b2a = (const float*)d_in[10];
    const float* W1b = (const float*)d_in[11];
    const float* b1b = (const float*)d_in[12];
    const float* g1b = (const float*)d_in[13];
    const float* be1b= (const float*)d_in[14];
    const float* m1b = (const float*)d_in[15];
    const float* v1b = (const float*)d_in[16];
    const float* W2b = (const float*)d_in[17];
    const float* b2b = (const float*)d_in[18];
    const float* lin1W = (const float*)d_in[19];
    const float* lin1b = (const float*)d_in[20];
    const float* lin2W = (const float*)d_in[21];
    const float* lin2b = (const float*)d_in[22];
    float* out = (float*)d_out;

    unsigned char *px, *pl0, *pl1, *hp1, *hp2, *wt;
    cudaGetSymbolAddress((void**)&px,  g_px);
    cudaGetSymbolAddress((void**)&pl0, g_pl0);
    cudaGetSymbolAddress((void**)&pl1, g_pl1);
    cudaGetSymbolAddress((void**)&hp1, g_hp1);
    cudaGetSymbolAddress((void**)&hp2, g_hp2);
    cudaGetSymbolAddress((void**)&wt,  g_wt);

    cudaFuncSetAttribute(gemm_mma_kernel<true>,  cudaFuncAttributeMaxDynamicSharedMemorySize, GSM_BYTES);
    cudaFuncSetAttribute(gemm_mma_kernel<false>, cudaFuncAttributeMaxDynamicSharedMemorySize, GSM_BYTES);

    dim3 gemmGrid(N_TILES, 2);
    const int aggGrid  = (N_NODES + 7) / 8;
    const int scanGrid = (N_NODES + 1023) / 1024; // 49

    // detect + zero counts
    detect_zero_kernel<<<(N_NODES + 255) / 256, 256>>>((const long long*)ei);

    // fused wconv + hist + pool-zero + xconv
    prep_kernel<<<WCONV_BLOCKS + HIST_BLOCKS + XCONV_BLOCKS, 256>>>(ei, x, W1a, W2a, W1b, W2b);

    // CSR build
    scan1_kernel<<<scanGrid, 1024>>>();
    scan3_kernel<<<scanGrid, 1024>>>(scanGrid);
    fill_kernel<<<(N_EDGES + 255) / 256, 256>>>(ei);

    // layer 1
    agg_kernel<<<aggGrid, 256>>>(px, pl0);
    gemm_mma_kernel<true ><<<gemmGrid, 256, GSM_BYTES>>>(
        pl0, wt + 0 * 131072, b1a, g1a, be1a, m1a, v1a, pl1, N_NODES);
    gemm_mma_kernel<false><<<gemmGrid, 256, GSM_BYTES>>>(
        pl1, wt + 1 * 131072, b2a, nullptr, nullptr, nullptr, nullptr, hp1, N_NODES);

    // layer 2
    agg_kernel<<<aggGrid, 256>>>(hp1, pl0);
    gemm_mma_kernel<true ><<<gemmGrid, 256, GSM_BYTES>>>(
        pl0, wt + 2 * 131072, b1b, g1b, be1b, m1b, v1b, pl1, N_NODES);
    gemm_mma_kernel<false><<<gemmGrid, 256, GSM_BYTES>>>(
        pl1, wt + 3 * 131072, b2b, nullptr, nullptr, nullptr, nullptr, hp2, N_NODES);

    // pooling (g_pool zeroed inside prep_kernel)
    pool_kernel<<<((N_NODES + 15) / 16 + 7) / 8, 256>>>(hp1, hp2, batch);

    // head
    head_kernel<<<(N_GRAPHS + 7) / 8, 256>>>(lin1W, lin1b, lin2W, lin2b, out);
}